// round 1
// baseline (speedup 1.0000x reference)
#include <cuda_runtime.h>
#include <cstddef>

#define DM   512
#define NH   8
#define HD   64
#define PS   4
#define BB   4
#define TT   4096
#define PP   1024

// scratch (device globals; no allocation allowed)
__device__ float g_Q[(size_t)BB * TT * DM];   // 32 MB
__device__ float g_K[(size_t)BB * PP * DM];   //  8 MB
__device__ float g_V[(size_t)BB * PP * DM];   //  8 MB
__device__ float g_C[(size_t)BB * TT * DM];   // 32 MB (attention context)

// ---------------------------------------------------------------------------
// C[M,512] = A[M,512] @ W[512,512] + bias (+ optional residual)
// block = 64x64 tile, 256 threads, 4x4 register tile per thread
// ---------------------------------------------------------------------------
__global__ __launch_bounds__(256) void gemm_bias(
    const float* __restrict__ A, const float* __restrict__ W,
    const float* __restrict__ bias, const float* __restrict__ resid,
    float* __restrict__ C)
{
    __shared__ float As[64][33];
    __shared__ float Ws[32][68];

    const int tid = threadIdx.x;
    const int tx = tid & 15;        // 0..15 (col group)
    const int ty = tid >> 4;        // 0..15 (row group)
    const int m0 = blockIdx.y << 6;
    const int n0 = blockIdx.x << 6;

    float acc[4][4] = {};

    for (int k0 = 0; k0 < 512; k0 += 32) {
        #pragma unroll
        for (int i = 0; i < 8; i++) {
            int idx = tid + (i << 8);
            int r = idx >> 5, c = idx & 31;
            As[r][c] = A[(size_t)(m0 + r) * DM + k0 + c];
        }
        #pragma unroll
        for (int i = 0; i < 8; i++) {
            int idx = tid + (i << 8);
            int r = idx >> 6, c = idx & 63;
            Ws[r][c] = W[(size_t)(k0 + r) * DM + n0 + c];
        }
        __syncthreads();

        #pragma unroll
        for (int kk = 0; kk < 32; kk++) {
            float a[4];
            #pragma unroll
            for (int i = 0; i < 4; i++) a[i] = As[(ty << 2) + i][kk];
            float4 b4 = *(const float4*)&Ws[kk][tx << 2];
            float b[4] = {b4.x, b4.y, b4.z, b4.w};
            #pragma unroll
            for (int i = 0; i < 4; i++)
                #pragma unroll
                for (int j = 0; j < 4; j++)
                    acc[i][j] = fmaf(a[i], b[j], acc[i][j]);
        }
        __syncthreads();
    }

    #pragma unroll
    for (int i = 0; i < 4; i++) {
        const int m = m0 + (ty << 2) + i;
        #pragma unroll
        for (int j = 0; j < 4; j++) {
            const int n = n0 + (tx << 2) + j;
            float v = acc[i][j] + bias[n];
            if (resid) v += resid[(size_t)m * DM + n];
            C[(size_t)m * DM + n] = v;
        }
    }
}

// ---------------------------------------------------------------------------
// Flash attention with block-causal token->patch mask.
// grid = (T/64, H, B); block = 256 threads.
// thread t: row = t>>2 (query row in tile), tx = t&3 owns 16 output cols
// (cbase = tx*16). The 4 threads of a row are adjacent warp lanes ->
// softmax max/sum reduced with shfl_xor(1), shfl_xor(2).
// ---------------------------------------------------------------------------
__global__ __launch_bounds__(256) void attn_kernel(
    const float* __restrict__ Q, const float* __restrict__ K,
    const float* __restrict__ V, float* __restrict__ ctx)
{
    extern __shared__ float sm[];
    float (*Ks)[68] = (float(*)[68])sm;
    float (*Vs)[68] = (float(*)[68])(sm + 64 * 68);
    float (*Ps)[68] = (float(*)[68])(sm + 2 * 64 * 68);

    const int tid = threadIdx.x;
    const int b = blockIdx.z, h = blockIdx.y;
    const int t0 = blockIdx.x << 6;
    const int row = tid >> 2;
    const int tx = tid & 3;
    const int cbase = tx << 4;

    // q row (pre-scaled by 1/sqrt(64)) in registers
    float q[64];
    {
        const float* qp = Q + (size_t)(b * TT + t0 + row) * DM + h * HD;
        #pragma unroll
        for (int i = 0; i < 16; i++) {
            float4 v = *(const float4*)(qp + (i << 2));
            q[4 * i + 0] = v.x * 0.125f;
            q[4 * i + 1] = v.y * 0.125f;
            q[4 * i + 2] = v.z * 0.125f;
            q[4 * i + 3] = v.w * 0.125f;
        }
    }

    float m_run = -1e30f, l_run = 0.0f;
    float acc[16];
    #pragma unroll
    for (int i = 0; i < 16; i++) acc[i] = 0.0f;

    const int myLim = (t0 + row) >> 2;                 // last allowed patch
    const int nblocks = (((t0 + 63) >> 2) >> 6) + 1;   // patch blocks needed
    const float* Kb = K + (size_t)b * PP * DM + h * HD;
    const float* Vb = V + (size_t)b * PP * DM + h * HD;

    for (int kb = 0; kb < nblocks; kb++) {
        const int p0 = kb << 6;
        __syncthreads();   // prev iter's Ps/Vs reads done before overwrite
        #pragma unroll
        for (int i = 0; i < 4; i++) {
            int idx = tid + (i << 8);        // 1024 float4 slots: 64 rows x 16
            int r = idx >> 4, c4 = (idx & 15) << 2;
            *(float4*)&Ks[r][c4] = *(const float4*)(Kb + (size_t)(p0 + r) * DM + c4);
            *(float4*)&Vs[r][c4] = *(const float4*)(Vb + (size_t)(p0 + r) * DM + c4);
        }
        __syncthreads();

        // scores for own 16 cols -> registers
        float s[16];
        float mb = -1e30f;
        #pragma unroll
        for (int jj = 0; jj < 16; jj++) {
            const int j = cbase + jj;
            float acc_s = 0.0f;
            #pragma unroll
            for (int k4 = 0; k4 < 16; k4++) {
                float4 kv = *(const float4*)&Ks[j][k4 << 2];
                acc_s = fmaf(q[4 * k4 + 0], kv.x, acc_s);
                acc_s = fmaf(q[4 * k4 + 1], kv.y, acc_s);
                acc_s = fmaf(q[4 * k4 + 2], kv.z, acc_s);
                acc_s = fmaf(q[4 * k4 + 3], kv.w, acc_s);
            }
            if (p0 + j > myLim) acc_s = -1e30f;
            s[jj] = acc_s;
            mb = fmaxf(mb, acc_s);
        }
        // row max across the 4 lanes sharing this row
        mb = fmaxf(mb, __shfl_xor_sync(0xffffffffu, mb, 1));
        mb = fmaxf(mb, __shfl_xor_sync(0xffffffffu, mb, 2));

        const float m_new = fmaxf(m_run, mb);
        const float alpha = __expf(m_run - m_new);
        float lsum = 0.0f;
        #pragma unroll
        for (int jj = 0; jj < 16; jj++) {
            float p = __expf(s[jj] - m_new);
            Ps[row][cbase + jj] = p;
            lsum += p;
        }
        lsum += __shfl_xor_sync(0xffffffffu, lsum, 1);
        lsum += __shfl_xor_sync(0xffffffffu, lsum, 2);
        l_run = l_run * alpha + lsum;
        m_run = m_new;

        #pragma unroll
        for (int i = 0; i < 16; i++) acc[i] *= alpha;

        __syncthreads();   // all p's of the row visible before PV
        #pragma unroll 4
        for (int j = 0; j < 64; j++) {
            const float p = Ps[row][j];
            #pragma unroll
            for (int c4 = 0; c4 < 4; c4++) {
                float4 vv = *(const float4*)&Vs[j][cbase + (c4 << 2)];
                acc[c4 * 4 + 0] = fmaf(p, vv.x, acc[c4 * 4 + 0]);
                acc[c4 * 4 + 1] = fmaf(p, vv.y, acc[c4 * 4 + 1]);
                acc[c4 * 4 + 2] = fmaf(p, vv.z, acc[c4 * 4 + 2]);
                acc[c4 * 4 + 3] = fmaf(p, vv.w, acc[c4 * 4 + 3]);
            }
        }
    }

    const float inv = 1.0f / l_run;
    float* op = ctx + (size_t)(b * TT + t0 + row) * DM + h * HD + cbase;
    #pragma unroll
    for (int c4 = 0; c4 < 4; c4++) {
        float4 o;
        o.x = acc[c4 * 4 + 0] * inv;
        o.y = acc[c4 * 4 + 1] * inv;
        o.z = acc[c4 * 4 + 2] * inv;
        o.w = acc[c4 * 4 + 3] * inv;
        *(float4*)(op + (c4 << 2)) = o;
    }
}

// ---------------------------------------------------------------------------
extern "C" void kernel_launch(void* const* d_in, const int* in_sizes, int n_in,
                              void* d_out, int out_size)
{
    (void)in_sizes; (void)n_in; (void)out_size;
    const float* tok   = (const float*)d_in[0];
    const float* patch = (const float*)d_in[1];
    const float* Wq    = (const float*)d_in[2];
    const float* Wk    = (const float*)d_in[3];
    const float* Wv    = (const float*)d_in[4];
    const float* bq    = (const float*)d_in[5];
    const float* bk    = (const float*)d_in[6];
    const float* bv    = (const float*)d_in[7];
    const float* Wo    = (const float*)d_in[8];
    const float* bo    = (const float*)d_in[9];
    float* out = (float*)d_out;

    float *pQ, *pK, *pV, *pC;
    cudaGetSymbolAddress((void**)&pQ, g_Q);
    cudaGetSymbolAddress((void**)&pK, g_K);
    cudaGetSymbolAddress((void**)&pV, g_V);
    cudaGetSymbolAddress((void**)&pC, g_C);

    const int attn_smem = 3 * 64 * 68 * (int)sizeof(float);  // 52224 B
    static bool attr_set = false;
    if (!attr_set) {
        cudaFuncSetAttribute(attn_kernel,
                             cudaFuncAttributeMaxDynamicSharedMemorySize,
                             attn_smem);
        attr_set = true;
    }

    // QKV projections
    gemm_bias<<<dim3(8, (BB * TT) / 64), 256>>>(tok,   Wq, bq, nullptr, pQ);
    gemm_bias<<<dim3(8, (BB * PP) / 64), 256>>>(patch, Wk, bk, nullptr, pK);
    gemm_bias<<<dim3(8, (BB * PP) / 64), 256>>>(patch, Wv, bv, nullptr, pV);

    // masked flash attention -> context
    attn_kernel<<<dim3(TT / 64, NH, BB), 256, attn_smem>>>(pQ, pK, pV, pC);

    // out projection + bias + residual
    gemm_bias<<<dim3(8, (BB * TT) / 64), 256>>>(pC, Wo, bo, tok, out);
}

// round 2
// speedup vs baseline: 3.0272x; 3.0272x over previous
#include <cuda_runtime.h>
#include <cstddef>

#define DM   512
#define NH   8
#define HD   64
#define PS   4
#define BB   4
#define TT   4096
#define PP   1024

// scratch (device globals; no allocation allowed)
__device__ float g_Q[(size_t)BB * TT * DM];   // 32 MB
__device__ float g_K[(size_t)BB * PP * DM];   //  8 MB
__device__ float g_V[(size_t)BB * PP * DM];   //  8 MB
__device__ float g_C[(size_t)BB * TT * DM];   // 32 MB (attention context)

// ---------------------------------------------------------------------------
// C[M,512] = A[M,512] @ W[512,512] + bias (+ optional residual)
// block = 64x64 tile, 256 threads, 4x4 register tile per thread
// ---------------------------------------------------------------------------
__global__ __launch_bounds__(256) void gemm_bias(
    const float* __restrict__ A, const float* __restrict__ W,
    const float* __restrict__ bias, const float* __restrict__ resid,
    float* __restrict__ C)
{
    __shared__ float As[64][33];
    __shared__ float Ws[32][68];

    const int tid = threadIdx.x;
    const int tx = tid & 15;        // 0..15 (col group)
    const int ty = tid >> 4;        // 0..15 (row group)
    const int m0 = blockIdx.y << 6;
    const int n0 = blockIdx.x << 6;

    float acc[4][4] = {};

    for (int k0 = 0; k0 < 512; k0 += 32) {
        #pragma unroll
        for (int i = 0; i < 8; i++) {
            int idx = tid + (i << 8);
            int r = idx >> 5, c = idx & 31;
            As[r][c] = A[(size_t)(m0 + r) * DM + k0 + c];
        }
        #pragma unroll
        for (int i = 0; i < 8; i++) {
            int idx = tid + (i << 8);
            int r = idx >> 6, c = idx & 63;
            Ws[r][c] = W[(size_t)(k0 + r) * DM + n0 + c];
        }
        __syncthreads();

        #pragma unroll
        for (int kk = 0; kk < 32; kk++) {
            float a[4];
            #pragma unroll
            for (int i = 0; i < 4; i++) a[i] = As[(ty << 2) + i][kk];
            float4 b4 = *(const float4*)&Ws[kk][tx << 2];
            float b[4] = {b4.x, b4.y, b4.z, b4.w};
            #pragma unroll
            for (int i = 0; i < 4; i++)
                #pragma unroll
                for (int j = 0; j < 4; j++)
                    acc[i][j] = fmaf(a[i], b[j], acc[i][j]);
        }
        __syncthreads();
    }

    #pragma unroll
    for (int i = 0; i < 4; i++) {
        const int m = m0 + (ty << 2) + i;
        #pragma unroll
        for (int j = 0; j < 4; j++) {
            const int n = n0 + (tx << 2) + j;
            float v = acc[i][j] + bias[n];
            if (resid) v += resid[(size_t)m * DM + n];
            C[(size_t)m * DM + n] = v;
        }
    }
}

// ---------------------------------------------------------------------------
// Flash attention with block-causal token->patch mask.
// grid = (T/64, H, B); block = 256 threads.
// Both the QK^T and PV products are 64x64x64 GEMMs with 4x4 register tiles:
//   thread (ty = tid>>4, tx = tid&15) owns rows 4ty..4ty+3, cols 4tx..4tx+3.
// Row-softmax reductions shuffle across the 16-lane tx group.
// smem (dynamic, pad 68 floats => 272B rows, float4-aligned):
//   Qt[k][row]  - Q tile transposed   (loaded once per block)
//   Kt[k][col]  - K tile transposed   (per iter)
//   Vs[p][c]    - V tile natural      (per iter)
//   Pt[p][row]  - probs transposed    (per iter)
// ---------------------------------------------------------------------------
#define APAD 68
__global__ __launch_bounds__(256, 2) void attn_kernel(
    const float* __restrict__ Q, const float* __restrict__ K,
    const float* __restrict__ V, float* __restrict__ ctx)
{
    extern __shared__ float sm[];
    float (*Qt)[APAD] = (float(*)[APAD])sm;
    float (*Kt)[APAD] = (float(*)[APAD])(sm + 64 * APAD);
    float (*Vs)[APAD] = (float(*)[APAD])(sm + 2 * 64 * APAD);
    float (*Pt)[APAD] = (float(*)[APAD])(sm + 3 * 64 * APAD);

    const int tid = threadIdx.x;
    const int b = blockIdx.z, h = blockIdx.y;
    const int t0 = blockIdx.x << 6;
    const int tx = tid & 15;
    const int ty = tid >> 4;
    const int r0 = ty << 2;   // first owned row
    const int c0 = tx << 2;   // first owned col

    // ---- load Q tile transposed (scaled by 1/sqrt(HD)=0.125) ----
    {
        const float* Qb = Q + (size_t)(b * TT + t0) * DM + h * HD;
        #pragma unroll
        for (int i = 0; i < 16; i++) {
            int idx = tid + (i << 8);
            int r = idx >> 6, c = idx & 63;
            Qt[c][r] = Qb[(size_t)r * DM + c] * 0.125f;
        }
    }

    float m_run[4], l_run[4], oacc[4][4];
    #pragma unroll
    for (int i = 0; i < 4; i++) {
        m_run[i] = -1e30f; l_run[i] = 0.0f;
        #pragma unroll
        for (int j = 0; j < 4; j++) oacc[i][j] = 0.0f;
    }

    const int nblocks = (((t0 + 63) >> 2) >> 6) + 1;   // patch tiles needed
    const float* Kb = K + (size_t)b * PP * DM + h * HD;
    const float* Vb = V + (size_t)b * PP * DM + h * HD;

    for (int kb = 0; kb < nblocks; kb++) {
        const int p0 = kb << 6;
        __syncthreads();   // prev iter's Pt/Vs/Kt reads done before overwrite
        // K tile transposed: Kt[k][patch]
        #pragma unroll
        for (int i = 0; i < 16; i++) {
            int idx = tid + (i << 8);
            int r = idx >> 6, c = idx & 63;
            Kt[c][r] = Kb[(size_t)(p0 + r) * DM + c];
        }
        // V tile natural, float4
        #pragma unroll
        for (int i = 0; i < 4; i++) {
            int idx = tid + (i << 8);       // 1024 float4 slots
            int r = idx >> 4, c4 = (idx & 15) << 2;
            *(float4*)&Vs[r][c4] = *(const float4*)(Vb + (size_t)(p0 + r) * DM + c4);
        }
        __syncthreads();

        // ---- scores: S = Qt^T * Kt  (64x64x64, 4x4/thread) ----
        float s[4][4];
        #pragma unroll
        for (int i = 0; i < 4; i++)
            #pragma unroll
            for (int j = 0; j < 4; j++) s[i][j] = 0.0f;

        #pragma unroll 16
        for (int k = 0; k < 64; k++) {
            float4 a4 = *(const float4*)&Qt[k][r0];
            float4 b4 = *(const float4*)&Kt[k][c0];
            float a[4] = {a4.x, a4.y, a4.z, a4.w};
            float bb[4] = {b4.x, b4.y, b4.z, b4.w};
            #pragma unroll
            for (int i = 0; i < 4; i++)
                #pragma unroll
                for (int j = 0; j < 4; j++)
                    s[i][j] = fmaf(a[i], bb[j], s[i][j]);
        }

        // ---- mask + online softmax (per owned row i) ----
        #pragma unroll
        for (int i = 0; i < 4; i++) {
            const int lim = (t0 + r0 + i) >> 2;     // last allowed patch
            float mb = -1e30f;
            #pragma unroll
            for (int j = 0; j < 4; j++) {
                if (p0 + c0 + j > lim) s[i][j] = -1e30f;
                mb = fmaxf(mb, s[i][j]);
            }
            mb = fmaxf(mb, __shfl_xor_sync(0xffffffffu, mb, 1));
            mb = fmaxf(mb, __shfl_xor_sync(0xffffffffu, mb, 2));
            mb = fmaxf(mb, __shfl_xor_sync(0xffffffffu, mb, 4));
            mb = fmaxf(mb, __shfl_xor_sync(0xffffffffu, mb, 8));

            const float m_new = fmaxf(m_run[i], mb);
            const float alpha = __expf(m_run[i] - m_new);
            float lsum = 0.0f;
            float p[4];
            #pragma unroll
            for (int j = 0; j < 4; j++) {
                p[j] = __expf(s[i][j] - m_new);
                lsum += p[j];
            }
            lsum += __shfl_xor_sync(0xffffffffu, lsum, 1);
            lsum += __shfl_xor_sync(0xffffffffu, lsum, 2);
            lsum += __shfl_xor_sync(0xffffffffu, lsum, 4);
            lsum += __shfl_xor_sync(0xffffffffu, lsum, 8);
            l_run[i] = l_run[i] * alpha + lsum;
            m_run[i] = m_new;
            #pragma unroll
            for (int j = 0; j < 4; j++) {
                oacc[i][j] *= alpha;
                s[i][j] = p[j];     // reuse s[] as prob storage
            }
        }

        // write probs transposed: Pt[p][row], float4 per owned col j
        #pragma unroll
        for (int j = 0; j < 4; j++) {
            float4 pv = make_float4(s[0][j], s[1][j], s[2][j], s[3][j]);
            *(float4*)&Pt[c0 + j][r0] = pv;
        }
        __syncthreads();

        // ---- O += P * V  (64x64x64, 4x4/thread) ----
        #pragma unroll 16
        for (int p = 0; p < 64; p++) {
            float4 a4 = *(const float4*)&Pt[p][r0];
            float4 b4 = *(const float4*)&Vs[p][c0];
            float a[4] = {a4.x, a4.y, a4.z, a4.w};
            float bb[4] = {b4.x, b4.y, b4.z, b4.w};
            #pragma unroll
            for (int i = 0; i < 4; i++)
                #pragma unroll
                for (int j = 0; j < 4; j++)
                    oacc[i][j] = fmaf(a[i], bb[j], oacc[i][j]);
        }
    }

    // ---- normalize + store ----
    #pragma unroll
    for (int i = 0; i < 4; i++) {
        const float inv = 1.0f / l_run[i];
        float4 o;
        o.x = oacc[i][0] * inv;
        o.y = oacc[i][1] * inv;
        o.z = oacc[i][2] * inv;
        o.w = oacc[i][3] * inv;
        *(float4*)(ctx + (size_t)(b * TT + t0 + r0 + i) * DM + h * HD + c0) = o;
    }
}

// ---------------------------------------------------------------------------
extern "C" void kernel_launch(void* const* d_in, const int* in_sizes, int n_in,
                              void* d_out, int out_size)
{
    (void)in_sizes; (void)n_in; (void)out_size;
    const float* tok   = (const float*)d_in[0];
    const float* patch = (const float*)d_in[1];
    const float* Wq    = (const float*)d_in[2];
    const float* Wk    = (const float*)d_in[3];
    const float* Wv    = (const float*)d_in[4];
    const float* bq    = (const float*)d_in[5];
    const float* bk    = (const float*)d_in[6];
    const float* bv    = (const float*)d_in[7];
    const float* Wo    = (const float*)d_in[8];
    const float* bo    = (const float*)d_in[9];
    float* out = (float*)d_out;

    float *pQ, *pK, *pV, *pC;
    cudaGetSymbolAddress((void**)&pQ, g_Q);
    cudaGetSymbolAddress((void**)&pK, g_K);
    cudaGetSymbolAddress((void**)&pV, g_V);
    cudaGetSymbolAddress((void**)&pC, g_C);

    const int attn_smem = 4 * 64 * APAD * (int)sizeof(float);  // 69632 B
    static bool attr_set = false;
    if (!attr_set) {
        cudaFuncSetAttribute(attn_kernel,
                             cudaFuncAttributeMaxDynamicSharedMemorySize,
                             attn_smem);
        attr_set = true;
    }

    // QKV projections
    gemm_bias<<<dim3(8, (BB * TT) / 64), 256>>>(tok,   Wq, bq, nullptr, pQ);
    gemm_bias<<<dim3(8, (BB * PP) / 64), 256>>>(patch, Wk, bk, nullptr, pK);
    gemm_bias<<<dim3(8, (BB * PP) / 64), 256>>>(patch, Wv, bv, nullptr, pV);

    // masked flash attention -> context
    attn_kernel<<<dim3(TT / 64, NH, BB), 256, attn_smem>>>(pQ, pK, pV, pC);

    // out projection + bias + residual
    gemm_bias<<<dim3(8, (BB * TT) / 64), 256>>>(pC, Wo, bo, tok, out);
}

// round 8
// speedup vs baseline: 4.5473x; 1.5022x over previous
#include <cuda_runtime.h>
#include <cuda_bf16.h>
#include <cstdint>
#include <cstddef>

#define DM   512
#define NH   8
#define HD   64
#define PS   4
#define BB   4
#define TT   4096
#define PP   1024

// ---------------------------------------------------------------------------
// scratch (device globals; no allocation allowed)
// ---------------------------------------------------------------------------
__device__ __align__(16) float g_Q[(size_t)BB * TT * DM];
__device__ __align__(16) float g_K[(size_t)BB * PP * DM];
__device__ __align__(16) float g_V[(size_t)BB * PP * DM];
__device__ __align__(16) float g_C[(size_t)BB * TT * DM];

__device__ __align__(16) __nv_bfloat16 g_tok_hi[(size_t)BB * TT * DM];
__device__ __align__(16) __nv_bfloat16 g_tok_lo[(size_t)BB * TT * DM];
__device__ __align__(16) __nv_bfloat16 g_pat_hi[(size_t)BB * PP * DM];
__device__ __align__(16) __nv_bfloat16 g_pat_lo[(size_t)BB * PP * DM];
__device__ __align__(16) __nv_bfloat16 g_ctx_hi[(size_t)BB * TT * DM];
__device__ __align__(16) __nv_bfloat16 g_ctx_lo[(size_t)BB * TT * DM];
__device__ __align__(16) __nv_bfloat16 g_Wt_hi[4 * DM * DM];
__device__ __align__(16) __nv_bfloat16 g_Wt_lo[4 * DM * DM];

// ---------------------------------------------------------------------------
// base-ISA tensor-core helpers (work on plain sm_103 target)
// ---------------------------------------------------------------------------
__device__ __forceinline__ uint32_t smem_u32(const void* p) {
    uint32_t a;
    asm("{ .reg .u64 t; cvta.to.shared.u64 t, %1; cvt.u32.u64 %0, t; }"
        : "=r"(a) : "l"(p));
    return a;
}

__device__ __forceinline__ void ldsm_x4(uint32_t& r0, uint32_t& r1,
                                        uint32_t& r2, uint32_t& r3, uint32_t addr) {
    asm volatile("ldmatrix.sync.aligned.m8n8.x4.shared.b16 {%0,%1,%2,%3}, [%4];"
                 : "=r"(r0), "=r"(r1), "=r"(r2), "=r"(r3) : "r"(addr));
}

__device__ __forceinline__ void mma16816(float* d, const uint32_t* a, const uint32_t* b) {
    asm volatile(
        "mma.sync.aligned.m16n8k16.row.col.f32.bf16.bf16.f32 "
        "{%0,%1,%2,%3}, {%4,%5,%6,%7}, {%8,%9}, {%0,%1,%2,%3};"
        : "+f"(d[0]), "+f"(d[1]), "+f"(d[2]), "+f"(d[3])
        : "r"(a[0]), "r"(a[1]), "r"(a[2]), "r"(a[3]), "r"(b[0]), "r"(b[1]));
}

// ---------------------------------------------------------------------------
// fp32 -> (bf16 hi, bf16 lo) split, vectorized
// ---------------------------------------------------------------------------
__global__ void conv_hilo(const float4* __restrict__ x,
                          __nv_bfloat162* __restrict__ hi,
                          __nv_bfloat162* __restrict__ lo, int n4)
{
    int i = blockIdx.x * blockDim.x + threadIdx.x;
    if (i >= n4) return;
    float4 v = x[i];
    __nv_bfloat16 h0 = __float2bfloat16_rn(v.x);
    __nv_bfloat16 h1 = __float2bfloat16_rn(v.y);
    __nv_bfloat16 h2 = __float2bfloat16_rn(v.z);
    __nv_bfloat16 h3 = __float2bfloat16_rn(v.w);
    hi[2 * i + 0] = __halves2bfloat162(h0, h1);
    hi[2 * i + 1] = __halves2bfloat162(h2, h3);
    lo[2 * i + 0] = __halves2bfloat162(
        __float2bfloat16_rn(v.x - __bfloat162float(h0)),
        __float2bfloat16_rn(v.y - __bfloat162float(h1)));
    lo[2 * i + 1] = __halves2bfloat162(
        __float2bfloat16_rn(v.z - __bfloat162float(h2)),
        __float2bfloat16_rn(v.w - __bfloat162float(h3)));
}

// ---------------------------------------------------------------------------
// W[512,512] -> transposed hi/lo bf16: Wt[n][k] = W[k][n]
// grid (16,16), block (32,8)
// ---------------------------------------------------------------------------
__global__ void conv_wt(const float* __restrict__ W,
                        __nv_bfloat16* __restrict__ wht,
                        __nv_bfloat16* __restrict__ wlt)
{
    __shared__ float t[32][33];
    const int k0 = blockIdx.y * 32, n0 = blockIdx.x * 32;
    const int tx = threadIdx.x, ty = threadIdx.y;
    #pragma unroll
    for (int j = ty; j < 32; j += 8)
        t[j][tx] = W[(size_t)(k0 + j) * DM + n0 + tx];
    __syncthreads();
    #pragma unroll
    for (int j = ty; j < 32; j += 8) {
        float v = t[tx][j];                        // W[k0+tx][n0+j]
        __nv_bfloat16 h = __float2bfloat16_rn(v);
        wht[(size_t)(n0 + j) * DM + k0 + tx] = h;
        wlt[(size_t)(n0 + j) * DM + k0 + tx] =
            __float2bfloat16_rn(v - __bfloat162float(h));
    }
}

// ---------------------------------------------------------------------------
// HMMA split-bf16 GEMM: C[M,512] = A @ W + bias (+resid)
// A hi/lo: [M,512] bf16 row-major;  B hi/lo: Wt[n][k] bf16 (row = n, K-major)
// 3-term: Ahi*Bhi + Ahi*Blo + Alo*Bhi, fp32 accum (HMMA.16816)
// CTA tile 128(m) x 128(n), 8 warps (2m x 4n), warp tile 64x32.
// K chunk 64. smem rows padded to 144 B (conflict-free ldmatrix).
// grid = (4, M/128), block 256
// ---------------------------------------------------------------------------
#define GP     144                         // smem row pitch, bytes
#define OFF_AH 0
#define OFF_AL (128 * GP)
#define OFF_BH (2 * 128 * GP)
#define OFF_BL (3 * 128 * GP)
#define GSMEM  (4 * 128 * GP)              // 73728 B

__global__ __launch_bounds__(256) void gemm_hmma(
    const __nv_bfloat16* __restrict__ Ahi, const __nv_bfloat16* __restrict__ Alo,
    const __nv_bfloat16* __restrict__ Bhi, const __nv_bfloat16* __restrict__ Blo,
    const float* __restrict__ bias, const float* __restrict__ resid,
    float* __restrict__ C)
{
    extern __shared__ char smg[];
    const uint32_t sb = smem_u32(smg);
    const int tid = threadIdx.x, wid = tid >> 5, lid = tid & 31;
    const int wm = wid >> 2, wn = wid & 3;           // warp 2x4
    const int m0 = blockIdx.y << 7, n0 = blockIdx.x << 7;

    const char* gAh = (const char*)(Ahi + (size_t)m0 * DM);
    const char* gAl = (const char*)(Alo + (size_t)m0 * DM);
    const char* gBh = (const char*)(Bhi + (size_t)n0 * DM);
    const char* gBl = (const char*)(Blo + (size_t)n0 * DM);

    float acc[4][4][4];
    #pragma unroll
    for (int i = 0; i < 4; i++)
        #pragma unroll
        for (int j = 0; j < 4; j++)
            #pragma unroll
            for (int c = 0; c < 4; c++) acc[i][j][c] = 0.0f;

    // ldmatrix lane addresses (constant across chunks except k offset)
    const int a_row = (wm << 6) + (lid & 15);        // + mt*16
    const int a_cb  = (lid >> 4) << 4;               // byte offset of 8-col half
    const int b_sub = lid >> 3;
    const int b_row = (wn << 5) + ((b_sub & 1) << 3) + (lid & 7);  // + pair*16
    const int b_cb  = (b_sub >> 1) << 4;

    for (int ck = 0; ck < 8; ck++) {
        const size_t koff = (size_t)ck << 7;         // 64 bf16 = 128 B
        __syncthreads();
        #pragma unroll
        for (int i = 0; i < 4; i++) {
            int idx = tid + (i << 8);
            int r = idx >> 3, cb = (idx & 7) << 4;
            size_t go = (size_t)r * (DM * 2) + koff + cb;
            uint32_t so = r * GP + cb;
            *(uint4*)(smg + OFF_AH + so) = *(const uint4*)(gAh + go);
            *(uint4*)(smg + OFF_AL + so) = *(const uint4*)(gAl + go);
            *(uint4*)(smg + OFF_BH + so) = *(const uint4*)(gBh + go);
            *(uint4*)(smg + OFF_BL + so) = *(const uint4*)(gBl + go);
        }
        __syncthreads();

        #pragma unroll
        for (int ks = 0; ks < 4; ks++) {
            const int kb = ks << 5;                  // 16 bf16 = 32 B

            uint32_t ah[4][4], al[4][4];
            #pragma unroll
            for (int mt = 0; mt < 4; mt++) {
                uint32_t ad = sb + (a_row + (mt << 4)) * GP + kb + a_cb;
                ldsm_x4(ah[mt][0], ah[mt][1], ah[mt][2], ah[mt][3], OFF_AH + ad);
                ldsm_x4(al[mt][0], al[mt][1], al[mt][2], al[mt][3], OFF_AL + ad);
            }
            uint32_t bh[4][2], bl[4][2];
            #pragma unroll
            for (int pr = 0; pr < 2; pr++) {
                uint32_t bd = sb + (b_row + (pr << 4)) * GP + kb + b_cb;
                uint32_t r0, r1, r2, r3;
                ldsm_x4(r0, r1, r2, r3, OFF_BH + bd);
                bh[2 * pr][0] = r0; bh[2 * pr + 1][0] = r1;
                bh[2 * pr][1] = r2; bh[2 * pr + 1][1] = r3;
                ldsm_x4(r0, r1, r2, r3, OFF_BL + bd);
                bl[2 * pr][0] = r0; bl[2 * pr + 1][0] = r1;
                bl[2 * pr][1] = r2; bl[2 * pr + 1][1] = r3;
            }

            #pragma unroll
            for (int mt = 0; mt < 4; mt++)
                #pragma unroll
                for (int nt = 0; nt < 4; nt++) {
                    mma16816(acc[mt][nt], ah[mt], bh[nt]);
                    mma16816(acc[mt][nt], ah[mt], bl[nt]);
                    mma16816(acc[mt][nt], al[mt], bh[nt]);
                }
        }
    }

    // epilogue: fragment rows (groupID, groupID+8), cols 2*(lid&3)+{0,1}
    #pragma unroll
    for (int mt = 0; mt < 4; mt++) {
        const int row0 = m0 + (wm << 6) + (mt << 4) + (lid >> 2);
        #pragma unroll
        for (int nt = 0; nt < 4; nt++) {
            const int col = n0 + (wn << 5) + (nt << 3) + ((lid & 3) << 1);
            const float b0 = bias[col], b1 = bias[col + 1];
            float2 o0 = make_float2(acc[mt][nt][0] + b0, acc[mt][nt][1] + b1);
            float2 o1 = make_float2(acc[mt][nt][2] + b0, acc[mt][nt][3] + b1);
            if (resid) {
                const float2 r0 = *(const float2*)&resid[(size_t)row0 * DM + col];
                const float2 r1 = *(const float2*)&resid[(size_t)(row0 + 8) * DM + col];
                o0.x += r0.x; o0.y += r0.y;
                o1.x += r1.x; o1.y += r1.y;
            }
            *(float2*)&C[(size_t)row0 * DM + col] = o0;
            *(float2*)&C[(size_t)(row0 + 8) * DM + col] = o1;
        }
    }
}

// ---------------------------------------------------------------------------
// Flash attention with block-causal token->patch mask (fp32, proven).
// ---------------------------------------------------------------------------
#define APAD 68
__global__ __launch_bounds__(256, 2) void attn_kernel(
    const float* __restrict__ Q, const float* __restrict__ K,
    const float* __restrict__ V, float* __restrict__ ctx)
{
    extern __shared__ float sm[];
    float (*Qt)[APAD] = (float(*)[APAD])sm;
    float (*Kt)[APAD] = (float(*)[APAD])(sm + 64 * APAD);
    float (*Vs)[APAD] = (float(*)[APAD])(sm + 2 * 64 * APAD);
    float (*Pt)[APAD] = (float(*)[APAD])(sm + 3 * 64 * APAD);

    const int tid = threadIdx.x;
    const int b = blockIdx.z, h = blockIdx.y;
    const int t0 = blockIdx.x << 6;
    const int tx = tid & 15;
    const int ty = tid >> 4;
    const int r0 = ty << 2;
    const int c0 = tx << 2;

    {
        const float* Qb = Q + (size_t)(b * TT + t0) * DM + h * HD;
        #pragma unroll
        for (int i = 0; i < 16; i++) {
            int idx = tid + (i << 8);
            int r = idx >> 6, c = idx & 63;
            Qt[c][r] = Qb[(size_t)r * DM + c] * 0.125f;
        }
    }

    float m_run[4], l_run[4], oacc[4][4];
    #pragma unroll
    for (int i = 0; i < 4; i++) {
        m_run[i] = -1e30f; l_run[i] = 0.0f;
        #pragma unroll
        for (int j = 0; j < 4; j++) oacc[i][j] = 0.0f;
    }

    const int nblocks = (((t0 + 63) >> 2) >> 6) + 1;
    const float* Kb = K + (size_t)b * PP * DM + h * HD;
    const float* Vb = V + (size_t)b * PP * DM + h * HD;

    for (int kb = 0; kb < nblocks; kb++) {
        const int p0 = kb << 6;
        __syncthreads();
        #pragma unroll
        for (int i = 0; i < 16; i++) {
            int idx = tid + (i << 8);
            int r = idx >> 6, c = idx & 63;
            Kt[c][r] = Kb[(size_t)(p0 + r) * DM + c];
        }
        #pragma unroll
        for (int i = 0; i < 4; i++) {
            int idx = tid + (i << 8);
            int r = idx >> 4, c4 = (idx & 15) << 2;
            *(float4*)&Vs[r][c4] = *(const float4*)(Vb + (size_t)(p0 + r) * DM + c4);
        }
        __syncthreads();

        float s[4][4];
        #pragma unroll
        for (int i = 0; i < 4; i++)
            #pragma unroll
            for (int j = 0; j < 4; j++) s[i][j] = 0.0f;

        #pragma unroll 16
        for (int k = 0; k < 64; k++) {
            float4 a4 = *(const float4*)&Qt[k][r0];
            float4 b4 = *(const float4*)&Kt[k][c0];
            float a[4] = {a4.x, a4.y, a4.z, a4.w};
            float bb[4] = {b4.x, b4.y, b4.z, b4.w};
            #pragma unroll
            for (int i = 0; i < 4; i++)
                #pragma unroll
                for (int j = 0; j < 4; j++)
                    s[i][j] = fmaf(a[i], bb[j], s[i][j]);
        }

        #pragma unroll
        for (int i = 0; i < 4; i++) {
            const int lim = (t0 + r0 + i) >> 2;
            float mb = -1e30f;
            #pragma unroll
            for (int j = 0; j < 4; j++) {
                if (p0 + c0 + j > lim) s[i][j] = -1e30f;
                mb = fmaxf(mb, s[i][j]);
            }
            mb = fmaxf(mb, __shfl_xor_sync(0xffffffffu, mb, 1));
            mb = fmaxf(mb, __shfl_xor_sync(0xffffffffu, mb, 2));
            mb = fmaxf(mb, __shfl_xor_sync(0xffffffffu, mb, 4));
            mb = fmaxf(mb, __shfl_xor_sync(0xffffffffu, mb, 8));

            const float m_new = fmaxf(m_run[i], mb);
            const float alpha = __expf(m_run[i] - m_new);
            float lsum = 0.0f;
            float p[4];
            #pragma unroll
            for (int j = 0; j < 4; j++) {
                p[j] = __expf(s[i][j] - m_new);
                lsum += p[j];
            }
            lsum += __shfl_xor_sync(0xffffffffu, lsum, 1);
            lsum += __shfl_xor_sync(0xffffffffu, lsum, 2);
            lsum += __shfl_xor_sync(0xffffffffu, lsum, 4);
            lsum += __shfl_xor_sync(0xffffffffu, lsum, 8);
            l_run[i] = l_run[i] * alpha + lsum;
            m_run[i] = m_new;
            #pragma unroll
            for (int j = 0; j < 4; j++) {
                oacc[i][j] *= alpha;
                s[i][j] = p[j];
            }
        }

        #pragma unroll
        for (int j = 0; j < 4; j++) {
            float4 pv = make_float4(s[0][j], s[1][j], s[2][j], s[3][j]);
            *(float4*)&Pt[c0 + j][r0] = pv;
        }
        __syncthreads();

        #pragma unroll 16
        for (int p = 0; p < 64; p++) {
            float4 a4 = *(const float4*)&Pt[p][r0];
            float4 b4 = *(const float4*)&Vs[p][c0];
            float a[4] = {a4.x, a4.y, a4.z, a4.w};
            float bb[4] = {b4.x, b4.y, b4.z, b4.w};
            #pragma unroll
            for (int i = 0; i < 4; i++)
                #pragma unroll
                for (int j = 0; j < 4; j++)
                    oacc[i][j] = fmaf(a[i], bb[j], oacc[i][j]);
        }
    }

    #pragma unroll
    for (int i = 0; i < 4; i++) {
        const float inv = 1.0f / l_run[i];
        float4 o;
        o.x = oacc[i][0] * inv;
        o.y = oacc[i][1] * inv;
        o.z = oacc[i][2] * inv;
        o.w = oacc[i][3] * inv;
        *(float4*)(ctx + (size_t)(b * TT + t0 + r0 + i) * DM + h * HD + c0) = o;
    }
}

// ---------------------------------------------------------------------------
extern "C" void kernel_launch(void* const* d_in, const int* in_sizes, int n_in,
                              void* d_out, int out_size)
{
    (void)in_sizes; (void)n_in; (void)out_size;
    const float* tok   = (const float*)d_in[0];
    const float* patch = (const float*)d_in[1];
    const float* Wq    = (const float*)d_in[2];
    const float* Wk    = (const float*)d_in[3];
    const float* Wv    = (const float*)d_in[4];
    const float* bq    = (const float*)d_in[5];
    const float* bk    = (const float*)d_in[6];
    const float* bv    = (const float*)d_in[7];
    const float* Wo    = (const float*)d_in[8];
    const float* bo    = (const float*)d_in[9];
    float* out = (float*)d_out;

    float *pQ, *pK, *pV, *pC;
    cudaGetSymbolAddress((void**)&pQ, g_Q);
    cudaGetSymbolAddress((void**)&pK, g_K);
    cudaGetSymbolAddress((void**)&pV, g_V);
    cudaGetSymbolAddress((void**)&pC, g_C);
    __nv_bfloat16 *tkh, *tkl, *pth, *ptl, *cxh, *cxl, *wth, *wtl;
    cudaGetSymbolAddress((void**)&tkh, g_tok_hi);
    cudaGetSymbolAddress((void**)&tkl, g_tok_lo);
    cudaGetSymbolAddress((void**)&pth, g_pat_hi);
    cudaGetSymbolAddress((void**)&ptl, g_pat_lo);
    cudaGetSymbolAddress((void**)&cxh, g_ctx_hi);
    cudaGetSymbolAddress((void**)&cxl, g_ctx_lo);
    cudaGetSymbolAddress((void**)&wth, g_Wt_hi);
    cudaGetSymbolAddress((void**)&wtl, g_Wt_lo);

    const int attn_smem = 4 * 64 * APAD * (int)sizeof(float);  // 69632 B
    static bool attr_set = false;
    if (!attr_set) {
        cudaFuncSetAttribute(attn_kernel,
                             cudaFuncAttributeMaxDynamicSharedMemorySize, attn_smem);
        cudaFuncSetAttribute(gemm_hmma,
                             cudaFuncAttributeMaxDynamicSharedMemorySize, GSMEM);
        attr_set = true;
    }

    const int nTok4 = BB * TT * DM / 4;   // 2097152
    const int nPat4 = BB * PP * DM / 4;   // 524288

    // split activations + weights into bf16 hi/lo
    conv_hilo<<<nTok4 / 256, 256>>>((const float4*)tok,
        (__nv_bfloat162*)tkh, (__nv_bfloat162*)tkl, nTok4);
    conv_hilo<<<nPat4 / 256, 256>>>((const float4*)patch,
        (__nv_bfloat162*)pth, (__nv_bfloat162*)ptl, nPat4);
    conv_wt<<<dim3(16, 16), dim3(32, 8)>>>(Wq, wth + 0 * DM * DM, wtl + 0 * DM * DM);
    conv_wt<<<dim3(16, 16), dim3(32, 8)>>>(Wk, wth + 1 * DM * DM, wtl + 1 * DM * DM);
    conv_wt<<<dim3(16, 16), dim3(32, 8)>>>(Wv, wth + 2 * DM * DM, wtl + 2 * DM * DM);
    conv_wt<<<dim3(16, 16), dim3(32, 8)>>>(Wo, wth + 3 * DM * DM, wtl + 3 * DM * DM);

    // QKV projections on HMMA tensor cores
    gemm_hmma<<<dim3(4, BB * TT / 128), 256, GSMEM>>>(
        tkh, tkl, wth + 0 * DM * DM, wtl + 0 * DM * DM, bq, nullptr, pQ);
    gemm_hmma<<<dim3(4, BB * PP / 128), 256, GSMEM>>>(
        pth, ptl, wth + 1 * DM * DM, wtl + 1 * DM * DM, bk, nullptr, pK);
    gemm_hmma<<<dim3(4, BB * PP / 128), 256, GSMEM>>>(
        pth, ptl, wth + 2 * DM * DM, wtl + 2 * DM * DM, bv, nullptr, pV);

    // masked flash attention -> context (fp32)
    attn_kernel<<<dim3(TT / 64, NH, BB), 256, attn_smem>>>(pQ, pK, pV, pC);

    // out projection + bias + residual on HMMA
    conv_hilo<<<nTok4 / 256, 256>>>((const float4*)pC,
        (__nv_bfloat162*)cxh, (__nv_bfloat162*)cxl, nTok4);
    gemm_hmma<<<dim3(4, BB * TT / 128), 256, GSMEM>>>(
        cxh, cxl, wth + 3 * DM * DM, wtl + 3 * DM * DM, bo, tok, out);
}

// round 9
// speedup vs baseline: 8.0355x; 1.7671x over previous
#include <cuda_runtime.h>
#include <cuda_bf16.h>
#include <cstdint>
#include <cstddef>

#define DM   512
#define NH   8
#define HD   64
#define PS   4
#define BB   4
#define TT   4096
#define PP   1024

// ---------------------------------------------------------------------------
// scratch (device globals; no allocation allowed)
// ---------------------------------------------------------------------------
__device__ __align__(16) __nv_bfloat16 g_Qh[(size_t)BB * TT * DM];
__device__ __align__(16) __nv_bfloat16 g_Ql[(size_t)BB * TT * DM];
__device__ __align__(16) __nv_bfloat16 g_Kh[(size_t)BB * PP * DM];
__device__ __align__(16) __nv_bfloat16 g_Kl[(size_t)BB * PP * DM];
__device__ __align__(16) __nv_bfloat16 g_Vh[(size_t)BB * PP * DM];
__device__ __align__(16) __nv_bfloat16 g_Vl[(size_t)BB * PP * DM];

__device__ __align__(16) __nv_bfloat16 g_tok_hi[(size_t)BB * TT * DM];
__device__ __align__(16) __nv_bfloat16 g_tok_lo[(size_t)BB * TT * DM];
__device__ __align__(16) __nv_bfloat16 g_pat_hi[(size_t)BB * PP * DM];
__device__ __align__(16) __nv_bfloat16 g_pat_lo[(size_t)BB * PP * DM];
__device__ __align__(16) __nv_bfloat16 g_ctx_hi[(size_t)BB * TT * DM];
__device__ __align__(16) __nv_bfloat16 g_ctx_lo[(size_t)BB * TT * DM];
__device__ __align__(16) __nv_bfloat16 g_Wt_hi[4 * DM * DM];
__device__ __align__(16) __nv_bfloat16 g_Wt_lo[4 * DM * DM];

// ---------------------------------------------------------------------------
// base-ISA tensor-core helpers (plain sm_103 target)
// ---------------------------------------------------------------------------
__device__ __forceinline__ uint32_t smem_u32(const void* p) {
    uint32_t a;
    asm("{ .reg .u64 t; cvta.to.shared.u64 t, %1; cvt.u32.u64 %0, t; }"
        : "=r"(a) : "l"(p));
    return a;
}

__device__ __forceinline__ void ldsm_x4(uint32_t& r0, uint32_t& r1,
                                        uint32_t& r2, uint32_t& r3, uint32_t addr) {
    asm volatile("ldmatrix.sync.aligned.m8n8.x4.shared.b16 {%0,%1,%2,%3}, [%4];"
                 : "=r"(r0), "=r"(r1), "=r"(r2), "=r"(r3) : "r"(addr));
}
__device__ __forceinline__ void ldsm_x4_t(uint32_t& r0, uint32_t& r1,
                                          uint32_t& r2, uint32_t& r3, uint32_t addr) {
    asm volatile("ldmatrix.sync.aligned.m8n8.x4.trans.shared.b16 {%0,%1,%2,%3}, [%4];"
                 : "=r"(r0), "=r"(r1), "=r"(r2), "=r"(r3) : "r"(addr));
}

__device__ __forceinline__ void mma16816(float* d, const uint32_t* a, const uint32_t* b) {
    asm volatile(
        "mma.sync.aligned.m16n8k16.row.col.f32.bf16.bf16.f32 "
        "{%0,%1,%2,%3}, {%4,%5,%6,%7}, {%8,%9}, {%0,%1,%2,%3};"
        : "+f"(d[0]), "+f"(d[1]), "+f"(d[2]), "+f"(d[3])
        : "r"(a[0]), "r"(a[1]), "r"(a[2]), "r"(a[3]), "r"(b[0]), "r"(b[1]));
}

__device__ __forceinline__ void split2(float v0, float v1, uint32_t& hi, uint32_t& lo) {
    __nv_bfloat16 h0 = __float2bfloat16_rn(v0);
    __nv_bfloat16 h1 = __float2bfloat16_rn(v1);
    __nv_bfloat162 hv = __halves2bfloat162(h0, h1);
    __nv_bfloat162 lv = __halves2bfloat162(
        __float2bfloat16_rn(v0 - __bfloat162float(h0)),
        __float2bfloat16_rn(v1 - __bfloat162float(h1)));
    hi = *(uint32_t*)&hv;
    lo = *(uint32_t*)&lv;
}

// ---------------------------------------------------------------------------
// fp32 -> (bf16 hi, bf16 lo) split, vectorized
// ---------------------------------------------------------------------------
__global__ void conv_hilo(const float4* __restrict__ x,
                          __nv_bfloat162* __restrict__ hi,
                          __nv_bfloat162* __restrict__ lo, int n4)
{
    int i = blockIdx.x * blockDim.x + threadIdx.x;
    if (i >= n4) return;
    float4 v = x[i];
    uint32_t h0, l0, h1, l1;
    split2(v.x, v.y, h0, l0);
    split2(v.z, v.w, h1, l1);
    hi[2 * i + 0] = *(__nv_bfloat162*)&h0;
    hi[2 * i + 1] = *(__nv_bfloat162*)&h1;
    lo[2 * i + 0] = *(__nv_bfloat162*)&l0;
    lo[2 * i + 1] = *(__nv_bfloat162*)&l1;
}

// ---------------------------------------------------------------------------
// W[512,512] -> transposed hi/lo bf16: Wt[n][k] = W[k][n]
// ---------------------------------------------------------------------------
__global__ void conv_wt(const float* __restrict__ W,
                        __nv_bfloat16* __restrict__ wht,
                        __nv_bfloat16* __restrict__ wlt)
{
    __shared__ float t[32][33];
    const int k0 = blockIdx.y * 32, n0 = blockIdx.x * 32;
    const int tx = threadIdx.x, ty = threadIdx.y;
    #pragma unroll
    for (int j = ty; j < 32; j += 8)
        t[j][tx] = W[(size_t)(k0 + j) * DM + n0 + tx];
    __syncthreads();
    #pragma unroll
    for (int j = ty; j < 32; j += 8) {
        float v = t[tx][j];
        __nv_bfloat16 h = __float2bfloat16_rn(v);
        wht[(size_t)(n0 + j) * DM + k0 + tx] = h;
        wlt[(size_t)(n0 + j) * DM + k0 + tx] =
            __float2bfloat16_rn(v - __bfloat162float(h));
    }
}

// ---------------------------------------------------------------------------
// HMMA split-bf16 GEMM, dual epilogue:
//   Cf != nullptr : fp32 out  = acc + bias (+resid)
//   Chi != nullptr: bf16 hi/lo split out (for Q/K/V feeding attention)
// ---------------------------------------------------------------------------
#define GP     144
#define OFF_AH 0
#define OFF_AL (128 * GP)
#define OFF_BH (2 * 128 * GP)
#define OFF_BL (3 * 128 * GP)
#define GSMEM  (4 * 128 * GP)              // 73728 B

__global__ __launch_bounds__(256) void gemm_hmma(
    const __nv_bfloat16* __restrict__ Ahi, const __nv_bfloat16* __restrict__ Alo,
    const __nv_bfloat16* __restrict__ Bhi, const __nv_bfloat16* __restrict__ Blo,
    const float* __restrict__ bias, const float* __restrict__ resid,
    float* __restrict__ Cf,
    __nv_bfloat16* __restrict__ Chi, __nv_bfloat16* __restrict__ Clo)
{
    extern __shared__ char smg[];
    const uint32_t sb = smem_u32(smg);
    const int tid = threadIdx.x, wid = tid >> 5, lid = tid & 31;
    const int wm = wid >> 2, wn = wid & 3;
    const int m0 = blockIdx.y << 7, n0 = blockIdx.x << 7;

    const char* gAh = (const char*)(Ahi + (size_t)m0 * DM);
    const char* gAl = (const char*)(Alo + (size_t)m0 * DM);
    const char* gBh = (const char*)(Bhi + (size_t)n0 * DM);
    const char* gBl = (const char*)(Blo + (size_t)n0 * DM);

    float acc[4][4][4];
    #pragma unroll
    for (int i = 0; i < 4; i++)
        #pragma unroll
        for (int j = 0; j < 4; j++)
            #pragma unroll
            for (int c = 0; c < 4; c++) acc[i][j][c] = 0.0f;

    const int a_row = (wm << 6) + (lid & 15);
    const int a_cb  = (lid >> 4) << 4;
    const int b_sub = lid >> 3;
    const int b_row = (wn << 5) + ((b_sub & 1) << 3) + (lid & 7);
    const int b_cb  = (b_sub >> 1) << 4;

    for (int ck = 0; ck < 8; ck++) {
        const size_t koff = (size_t)ck << 7;
        __syncthreads();
        #pragma unroll
        for (int i = 0; i < 4; i++) {
            int idx = tid + (i << 8);
            int r = idx >> 3, cb = (idx & 7) << 4;
            size_t go = (size_t)r * (DM * 2) + koff + cb;
            uint32_t so = r * GP + cb;
            *(uint4*)(smg + OFF_AH + so) = *(const uint4*)(gAh + go);
            *(uint4*)(smg + OFF_AL + so) = *(const uint4*)(gAl + go);
            *(uint4*)(smg + OFF_BH + so) = *(const uint4*)(gBh + go);
            *(uint4*)(smg + OFF_BL + so) = *(const uint4*)(gBl + go);
        }
        __syncthreads();

        #pragma unroll
        for (int ks = 0; ks < 4; ks++) {
            const int kb = ks << 5;

            uint32_t ah[4][4], al[4][4];
            #pragma unroll
            for (int mt = 0; mt < 4; mt++) {
                uint32_t ad = sb + (a_row + (mt << 4)) * GP + kb + a_cb;
                ldsm_x4(ah[mt][0], ah[mt][1], ah[mt][2], ah[mt][3], OFF_AH + ad);
                ldsm_x4(al[mt][0], al[mt][1], al[mt][2], al[mt][3], OFF_AL + ad);
            }
            uint32_t bh[4][2], bl[4][2];
            #pragma unroll
            for (int pr = 0; pr < 2; pr++) {
                uint32_t bd = sb + (b_row + (pr << 4)) * GP + kb + b_cb;
                uint32_t r0, r1, r2, r3;
                ldsm_x4(r0, r1, r2, r3, OFF_BH + bd);
                bh[2 * pr][0] = r0; bh[2 * pr + 1][0] = r1;
                bh[2 * pr][1] = r2; bh[2 * pr + 1][1] = r3;
                ldsm_x4(r0, r1, r2, r3, OFF_BL + bd);
                bl[2 * pr][0] = r0; bl[2 * pr + 1][0] = r1;
                bl[2 * pr][1] = r2; bl[2 * pr + 1][1] = r3;
            }

            #pragma unroll
            for (int mt = 0; mt < 4; mt++)
                #pragma unroll
                for (int nt = 0; nt < 4; nt++) {
                    mma16816(acc[mt][nt], ah[mt], bh[nt]);
                    mma16816(acc[mt][nt], ah[mt], bl[nt]);
                    mma16816(acc[mt][nt], al[mt], bh[nt]);
                }
        }
    }

    #pragma unroll
    for (int mt = 0; mt < 4; mt++) {
        const int row0 = m0 + (wm << 6) + (mt << 4) + (lid >> 2);
        #pragma unroll
        for (int nt = 0; nt < 4; nt++) {
            const int col = n0 + (wn << 5) + (nt << 3) + ((lid & 3) << 1);
            const float b0 = bias[col], b1 = bias[col + 1];
            float v00 = acc[mt][nt][0] + b0, v01 = acc[mt][nt][1] + b1;
            float v10 = acc[mt][nt][2] + b0, v11 = acc[mt][nt][3] + b1;
            if (Cf) {
                if (resid) {
                    const float2 r0 = *(const float2*)&resid[(size_t)row0 * DM + col];
                    const float2 r1 = *(const float2*)&resid[(size_t)(row0 + 8) * DM + col];
                    v00 += r0.x; v01 += r0.y; v10 += r1.x; v11 += r1.y;
                }
                *(float2*)&Cf[(size_t)row0 * DM + col] = make_float2(v00, v01);
                *(float2*)&Cf[(size_t)(row0 + 8) * DM + col] = make_float2(v10, v11);
            } else {
                uint32_t h, l;
                split2(v00, v01, h, l);
                *(uint32_t*)&Chi[(size_t)row0 * DM + col] = h;
                *(uint32_t*)&Clo[(size_t)row0 * DM + col] = l;
                split2(v10, v11, h, l);
                *(uint32_t*)&Chi[(size_t)(row0 + 8) * DM + col] = h;
                *(uint32_t*)&Clo[(size_t)(row0 + 8) * DM + col] = l;
            }
        }
    }
}

// ---------------------------------------------------------------------------
// HMMA flash attention, split-bf16 3-term, block-causal mask.
// grid (T/64, H, B), 128 threads (4 warps); warp w owns q rows [16w,16w+16).
// smem tiles (pitch 144 B): Qh Ql (once), Kh Kl Vh Vl (per iter), natural
// layouts; K B-frags via ldmatrix, V B-frags via ldmatrix.trans.
// Writes ctx directly as bf16 hi/lo.
// ---------------------------------------------------------------------------
#define ATP     144
#define AQH     0
#define AQL     (64 * ATP)
#define AKH     (2 * 64 * ATP)
#define AKL     (3 * 64 * ATP)
#define AVH     (4 * 64 * ATP)
#define AVL     (5 * 64 * ATP)
#define AT_SMEM (6 * 64 * ATP)          // 55296 B

__global__ __launch_bounds__(128) void attn_hmma(
    const __nv_bfloat16* __restrict__ Qh, const __nv_bfloat16* __restrict__ Ql,
    const __nv_bfloat16* __restrict__ Kh, const __nv_bfloat16* __restrict__ Kl,
    const __nv_bfloat16* __restrict__ Vh, const __nv_bfloat16* __restrict__ Vl,
    __nv_bfloat16* __restrict__ Ch, __nv_bfloat16* __restrict__ Cl)
{
    extern __shared__ char sma[];
    const uint32_t sb = smem_u32(sma);
    const int tid = threadIdx.x, wid = tid >> 5, lid = tid & 31;
    const int b = blockIdx.z, h = blockIdx.y;
    const int t0 = blockIdx.x << 6;

    // ---- load Q tile (64 x 64 bf16 hi/lo) ----
    {
        const char* gqh = (const char*)(Qh + (size_t)(b * TT + t0) * DM + h * HD);
        const char* gql = (const char*)(Ql + (size_t)(b * TT + t0) * DM + h * HD);
        #pragma unroll
        for (int i = 0; i < 8; i++) {
            int idx = tid + (i << 7);
            int r = idx >> 4, c8 = (idx & 15) << 3;
            *(uint2*)(sma + AQH + r * ATP + c8) = *(const uint2*)(gqh + (size_t)r * 1024 + c8);
            *(uint2*)(sma + AQL + r * ATP + c8) = *(const uint2*)(gql + (size_t)r * 1024 + c8);
        }
    }

    float S[8][4], O[8][4];
    #pragma unroll
    for (int nt = 0; nt < 8; nt++)
        #pragma unroll
        for (int e = 0; e < 4; e++) O[nt][e] = 0.0f;
    float mrun0 = -1e30f, mrun1 = -1e30f, lrun0 = 0.0f, lrun1 = 0.0f;

    const int nblocks = ((t0 + 63) >> 8) + 1;
    const char* gkh = (const char*)(Kh + (size_t)b * PP * DM + h * HD);
    const char* gkl = (const char*)(Kl + (size_t)b * PP * DM + h * HD);
    const char* gvh = (const char*)(Vh + (size_t)b * PP * DM + h * HD);
    const char* gvl = (const char*)(Vl + (size_t)b * PP * DM + h * HD);

    // fragment addresses (k-offset added per step)
    const uint32_t a_ad0 = sb + AQH + ((wid << 4) + (lid & 15)) * ATP + ((lid >> 4) << 4);
    const uint32_t b_row = ((lid >> 3) & 1) * 8 + (lid & 7);
    const uint32_t b_cb  = (lid >> 4) << 4;

    const int trow = t0 + (wid << 4) + (lid >> 2);
    const int lim0 = trow >> 2;
    const int lim1 = (trow + 8) >> 2;

    for (int kb = 0; kb < nblocks; kb++) {
        const int p0 = kb << 6;
        __syncthreads();
        #pragma unroll
        for (int i = 0; i < 8; i++) {
            int idx = tid + (i << 7);
            int r = idx >> 4, c8 = (idx & 15) << 3;
            size_t go = (size_t)r * 1024 + c8;
            uint32_t so = r * ATP + c8;
            *(uint2*)(sma + AKH + so) = *(const uint2*)(gkh + (size_t)p0 * 1024 + go);
            *(uint2*)(sma + AKL + so) = *(const uint2*)(gkl + (size_t)p0 * 1024 + go);
            *(uint2*)(sma + AVH + so) = *(const uint2*)(gvh + (size_t)p0 * 1024 + go);
            *(uint2*)(sma + AVL + so) = *(const uint2*)(gvl + (size_t)p0 * 1024 + go);
        }
        __syncthreads();

        // ---- scores S = (Q/8) K^T via 3-term HMMA ----
        #pragma unroll
        for (int nt = 0; nt < 8; nt++)
            #pragma unroll
            for (int e = 0; e < 4; e++) S[nt][e] = 0.0f;

        #pragma unroll
        for (int ks = 0; ks < 4; ks++) {
            const uint32_t kbyte = ks << 5;
            uint32_t ah[4], al[4];
            ldsm_x4(ah[0], ah[1], ah[2], ah[3], a_ad0 + kbyte);
            ldsm_x4(al[0], al[1], al[2], al[3], a_ad0 + (AQL - AQH) + kbyte);
            #pragma unroll
            for (int ntp = 0; ntp < 4; ntp++) {
                uint32_t bd = sb + AKH + ((ntp << 4) + b_row) * ATP + kbyte + b_cb;
                uint32_t r0, r1, r2, r3;
                uint32_t bh0[2], bh1[2], bl0[2], bl1[2];
                ldsm_x4(r0, r1, r2, r3, bd);
                bh0[0] = r0; bh1[0] = r1; bh0[1] = r2; bh1[1] = r3;
                ldsm_x4(r0, r1, r2, r3, bd + (AKL - AKH));
                bl0[0] = r0; bl1[0] = r1; bl0[1] = r2; bl1[1] = r3;
                mma16816(S[2 * ntp],     ah, bh0);
                mma16816(S[2 * ntp],     ah, bl0);
                mma16816(S[2 * ntp],     al, bh0);
                mma16816(S[2 * ntp + 1], ah, bh1);
                mma16816(S[2 * ntp + 1], ah, bl1);
                mma16816(S[2 * ntp + 1], al, bh1);
            }
        }

        // scale
        #pragma unroll
        for (int nt = 0; nt < 8; nt++)
            #pragma unroll
            for (int e = 0; e < 4; e++) S[nt][e] *= 0.125f;

        // mask (only possible in last block)
        if (kb == nblocks - 1) {
            const int cb = p0 + ((lid & 3) << 1);
            #pragma unroll
            for (int nt = 0; nt < 8; nt++) {
                const int c0 = cb + (nt << 3), c1 = c0 + 1;
                if (c0 > lim0) S[nt][0] = -1e30f;
                if (c1 > lim0) S[nt][1] = -1e30f;
                if (c0 > lim1) S[nt][2] = -1e30f;
                if (c1 > lim1) S[nt][3] = -1e30f;
            }
        }

        // ---- online softmax (rows trow, trow+8) ----
        float rm0 = -1e30f, rm1 = -1e30f;
        #pragma unroll
        for (int nt = 0; nt < 8; nt++) {
            rm0 = fmaxf(rm0, fmaxf(S[nt][0], S[nt][1]));
            rm1 = fmaxf(rm1, fmaxf(S[nt][2], S[nt][3]));
        }
        rm0 = fmaxf(rm0, __shfl_xor_sync(0xffffffffu, rm0, 1));
        rm0 = fmaxf(rm0, __shfl_xor_sync(0xffffffffu, rm0, 2));
        rm1 = fmaxf(rm1, __shfl_xor_sync(0xffffffffu, rm1, 1));
        rm1 = fmaxf(rm1, __shfl_xor_sync(0xffffffffu, rm1, 2));

        const float mn0 = fmaxf(mrun0, rm0), mn1 = fmaxf(mrun1, rm1);
        const float al0 = __expf(mrun0 - mn0), al1 = __expf(mrun1 - mn1);
        float s0 = 0.0f, s1 = 0.0f;
        #pragma unroll
        for (int nt = 0; nt < 8; nt++) {
            float p0e = __expf(S[nt][0] - mn0);
            float p1e = __expf(S[nt][1] - mn0);
            float p2e = __expf(S[nt][2] - mn1);
            float p3e = __expf(S[nt][3] - mn1);
            S[nt][0] = p0e; S[nt][1] = p1e; S[nt][2] = p2e; S[nt][3] = p3e;
            s0 += p0e + p1e; s1 += p2e + p3e;
            O[nt][0] *= al0; O[nt][1] *= al0;
            O[nt][2] *= al1; O[nt][3] *= al1;
        }
        s0 += __shfl_xor_sync(0xffffffffu, s0, 1);
        s0 += __shfl_xor_sync(0xffffffffu, s0, 2);
        s1 += __shfl_xor_sync(0xffffffffu, s1, 1);
        s1 += __shfl_xor_sync(0xffffffffu, s1, 2);
        lrun0 = lrun0 * al0 + s0; lrun1 = lrun1 * al1 + s1;
        mrun0 = mn0; mrun1 = mn1;

        // ---- O += P V  (P hi/lo packed from S fragments; V via trans ldsm) ----
        #pragma unroll
        for (int ks = 0; ks < 4; ks++) {
            const int nt0 = 2 * ks, nt1 = 2 * ks + 1;
            uint32_t aph[4], apl[4];
            split2(S[nt0][0], S[nt0][1], aph[0], apl[0]);
            split2(S[nt0][2], S[nt0][3], aph[1], apl[1]);
            split2(S[nt1][0], S[nt1][1], aph[2], apl[2]);
            split2(S[nt1][2], S[nt1][3], aph[3], apl[3]);

            #pragma unroll
            for (int nv = 0; nv < 4; nv++) {
                uint32_t vd = sb + AVH + ((ks << 4) + b_row) * ATP + (nv << 5) + b_cb;
                uint32_t r0, r1, r2, r3;
                uint32_t vh0[2], vh1[2], vl0[2], vl1[2];
                ldsm_x4_t(r0, r1, r2, r3, vd);
                vh0[0] = r0; vh0[1] = r1; vh1[0] = r2; vh1[1] = r3;
                ldsm_x4_t(r0, r1, r2, r3, vd + (AVL - AVH));
                vl0[0] = r0; vl0[1] = r1; vl1[0] = r2; vl1[1] = r3;
                mma16816(O[2 * nv],     aph, vh0);
                mma16816(O[2 * nv],     aph, vl0);
                mma16816(O[2 * nv],     apl, vh0);
                mma16816(O[2 * nv + 1], aph, vh1);
                mma16816(O[2 * nv + 1], aph, vl1);
                mma16816(O[2 * nv + 1], apl, vh1);
            }
        }
    }

    // ---- normalize + write ctx hi/lo ----
    const float inv0 = 1.0f / lrun0, inv1 = 1.0f / lrun1;
    const size_t row0 = (size_t)(b * TT) + trow;
    #pragma unroll
    for (int nt = 0; nt < 8; nt++) {
        const int col = h * HD + (nt << 3) + ((lid & 3) << 1);
        uint32_t hh, ll;
        split2(O[nt][0] * inv0, O[nt][1] * inv0, hh, ll);
        *(uint32_t*)&Ch[row0 * DM + col] = hh;
        *(uint32_t*)&Cl[row0 * DM + col] = ll;
        split2(O[nt][2] * inv1, O[nt][3] * inv1, hh, ll);
        *(uint32_t*)&Ch[(row0 + 8) * DM + col] = hh;
        *(uint32_t*)&Cl[(row0 + 8) * DM + col] = ll;
    }
}

// ---------------------------------------------------------------------------
extern "C" void kernel_launch(void* const* d_in, const int* in_sizes, int n_in,
                              void* d_out, int out_size)
{
    (void)in_sizes; (void)n_in; (void)out_size;
    const float* tok   = (const float*)d_in[0];
    const float* patch = (const float*)d_in[1];
    const float* Wq    = (const float*)d_in[2];
    const float* Wk    = (const float*)d_in[3];
    const float* Wv    = (const float*)d_in[4];
    const float* bq    = (const float*)d_in[5];
    const float* bk    = (const float*)d_in[6];
    const float* bv    = (const float*)d_in[7];
    const float* Wo    = (const float*)d_in[8];
    const float* bo    = (const float*)d_in[9];
    float* out = (float*)d_out;

    __nv_bfloat16 *qh, *ql, *kh, *kl, *vh, *vl;
    __nv_bfloat16 *tkh, *tkl, *pth, *ptl, *cxh, *cxl, *wth, *wtl;
    cudaGetSymbolAddress((void**)&qh,  g_Qh);
    cudaGetSymbolAddress((void**)&ql,  g_Ql);
    cudaGetSymbolAddress((void**)&kh,  g_Kh);
    cudaGetSymbolAddress((void**)&kl,  g_Kl);
    cudaGetSymbolAddress((void**)&vh,  g_Vh);
    cudaGetSymbolAddress((void**)&vl,  g_Vl);
    cudaGetSymbolAddress((void**)&tkh, g_tok_hi);
    cudaGetSymbolAddress((void**)&tkl, g_tok_lo);
    cudaGetSymbolAddress((void**)&pth, g_pat_hi);
    cudaGetSymbolAddress((void**)&ptl, g_pat_lo);
    cudaGetSymbolAddress((void**)&cxh, g_ctx_hi);
    cudaGetSymbolAddress((void**)&cxl, g_ctx_lo);
    cudaGetSymbolAddress((void**)&wth, g_Wt_hi);
    cudaGetSymbolAddress((void**)&wtl, g_Wt_lo);

    static bool attr_set = false;
    if (!attr_set) {
        cudaFuncSetAttribute(gemm_hmma,
                             cudaFuncAttributeMaxDynamicSharedMemorySize, GSMEM);
        cudaFuncSetAttribute(attn_hmma,
                             cudaFuncAttributeMaxDynamicSharedMemorySize, AT_SMEM);
        attr_set = true;
    }

    const int nTok4 = BB * TT * DM / 4;
    const int nPat4 = BB * PP * DM / 4;

    // split inputs into bf16 hi/lo
    conv_hilo<<<nTok4 / 256, 256>>>((const float4*)tok,
        (__nv_bfloat162*)tkh, (__nv_bfloat162*)tkl, nTok4);
    conv_hilo<<<nPat4 / 256, 256>>>((const float4*)patch,
        (__nv_bfloat162*)pth, (__nv_bfloat162*)ptl, nPat4);
    conv_wt<<<dim3(16, 16), dim3(32, 8)>>>(Wq, wth + 0 * DM * DM, wtl + 0 * DM * DM);
    conv_wt<<<dim3(16, 16), dim3(32, 8)>>>(Wk, wth + 1 * DM * DM, wtl + 1 * DM * DM);
    conv_wt<<<dim3(16, 16), dim3(32, 8)>>>(Wv, wth + 2 * DM * DM, wtl + 2 * DM * DM);
    conv_wt<<<dim3(16, 16), dim3(32, 8)>>>(Wo, wth + 3 * DM * DM, wtl + 3 * DM * DM);

    // QKV projections -> bf16 hi/lo outputs
    gemm_hmma<<<dim3(4, BB * TT / 128), 256, GSMEM>>>(
        tkh, tkl, wth + 0 * DM * DM, wtl + 0 * DM * DM, bq, nullptr,
        nullptr, qh, ql);
    gemm_hmma<<<dim3(4, BB * PP / 128), 256, GSMEM>>>(
        pth, ptl, wth + 1 * DM * DM, wtl + 1 * DM * DM, bk, nullptr,
        nullptr, kh, kl);
    gemm_hmma<<<dim3(4, BB * PP / 128), 256, GSMEM>>>(
        pth, ptl, wth + 2 * DM * DM, wtl + 2 * DM * DM, bv, nullptr,
        nullptr, vh, vl);

    // HMMA flash attention -> ctx hi/lo
    attn_hmma<<<dim3(TT / 64, NH, BB), 128, AT_SMEM>>>(
        qh, ql, kh, kl, vh, vl, cxh, cxl);

    // out projection + bias + residual -> fp32 output
    gemm_hmma<<<dim3(4, BB * TT / 128), 256, GSMEM>>>(
        cxh, cxl, wth + 3 * DM * DM, wtl + 3 * DM * DM, bo, tok,
        out, nullptr, nullptr);
}

// round 14
// speedup vs baseline: 8.4003x; 1.0454x over previous
#include <cuda_runtime.h>
#include <cuda_bf16.h>
#include <cstdint>
#include <cstddef>

#define DM   512
#define NH   8
#define HD   64
#define PS   4
#define BB   4
#define TT   4096
#define PP   1024

// ---------------------------------------------------------------------------
// scratch (device globals; no allocation allowed)
// ---------------------------------------------------------------------------
__device__ __align__(16) __nv_bfloat16 g_Qh[(size_t)BB * TT * DM];
__device__ __align__(16) __nv_bfloat16 g_Ql[(size_t)BB * TT * DM];
__device__ __align__(16) __nv_bfloat16 g_Kh[(size_t)BB * PP * DM];
__device__ __align__(16) __nv_bfloat16 g_Kl[(size_t)BB * PP * DM];
__device__ __align__(16) __nv_bfloat16 g_Vh[(size_t)BB * PP * DM];
__device__ __align__(16) __nv_bfloat16 g_Vl[(size_t)BB * PP * DM];

__device__ __align__(16) __nv_bfloat16 g_tok_hi[(size_t)BB * TT * DM];
__device__ __align__(16) __nv_bfloat16 g_tok_lo[(size_t)BB * TT * DM];
__device__ __align__(16) __nv_bfloat16 g_pat_hi[(size_t)BB * PP * DM];
__device__ __align__(16) __nv_bfloat16 g_pat_lo[(size_t)BB * PP * DM];
__device__ __align__(16) __nv_bfloat16 g_ctx_hi[(size_t)BB * TT * DM];
__device__ __align__(16) __nv_bfloat16 g_ctx_lo[(size_t)BB * TT * DM];
__device__ __align__(16) __nv_bfloat16 g_Wt_hi[4 * DM * DM];
__device__ __align__(16) __nv_bfloat16 g_Wt_lo[4 * DM * DM];

// ---------------------------------------------------------------------------
// base-ISA helpers (plain sm_103 target)
// ---------------------------------------------------------------------------
__device__ __forceinline__ uint32_t smem_u32(const void* p) {
    uint32_t a;
    asm("{ .reg .u64 t; cvta.to.shared.u64 t, %1; cvt.u32.u64 %0, t; }"
        : "=r"(a) : "l"(p));
    return a;
}

__device__ __forceinline__ void cp16(uint32_t saddr, const void* gaddr) {
    asm volatile("cp.async.cg.shared.global [%0], [%1], 16;"
                 :: "r"(saddr), "l"(gaddr));
}
__device__ __forceinline__ void cp_commit() {
    asm volatile("cp.async.commit_group;");
}
template <int N>
__device__ __forceinline__ void cp_wait() {
    asm volatile("cp.async.wait_group %0;" :: "n"(N));
}

__device__ __forceinline__ void ldsm_x4(uint32_t& r0, uint32_t& r1,
                                        uint32_t& r2, uint32_t& r3, uint32_t addr) {
    asm volatile("ldmatrix.sync.aligned.m8n8.x4.shared.b16 {%0,%1,%2,%3}, [%4];"
                 : "=r"(r0), "=r"(r1), "=r"(r2), "=r"(r3) : "r"(addr));
}
__device__ __forceinline__ void ldsm_x4_t(uint32_t& r0, uint32_t& r1,
                                          uint32_t& r2, uint32_t& r3, uint32_t addr) {
    asm volatile("ldmatrix.sync.aligned.m8n8.x4.trans.shared.b16 {%0,%1,%2,%3}, [%4];"
                 : "=r"(r0), "=r"(r1), "=r"(r2), "=r"(r3) : "r"(addr));
}

__device__ __forceinline__ void mma16816(float* d, const uint32_t* a, const uint32_t* b) {
    asm volatile(
        "mma.sync.aligned.m16n8k16.row.col.f32.bf16.bf16.f32 "
        "{%0,%1,%2,%3}, {%4,%5,%6,%7}, {%8,%9}, {%0,%1,%2,%3};"
        : "+f"(d[0]), "+f"(d[1]), "+f"(d[2]), "+f"(d[3])
        : "r"(a[0]), "r"(a[1]), "r"(a[2]), "r"(a[3]), "r"(b[0]), "r"(b[1]));
}

__device__ __forceinline__ void split2(float v0, float v1, uint32_t& hi, uint32_t& lo) {
    __nv_bfloat16 h0 = __float2bfloat16_rn(v0);
    __nv_bfloat16 h1 = __float2bfloat16_rn(v1);
    __nv_bfloat162 hv = __halves2bfloat162(h0, h1);
    __nv_bfloat162 lv = __halves2bfloat162(
        __float2bfloat16_rn(v0 - __bfloat162float(h0)),
        __float2bfloat16_rn(v1 - __bfloat162float(h1)));
    hi = *(uint32_t*)&hv;
    lo = *(uint32_t*)&lv;
}

// ---------------------------------------------------------------------------
// fp32 -> (bf16 hi, bf16 lo) split, vectorized
// ---------------------------------------------------------------------------
__global__ void conv_hilo(const float4* __restrict__ x,
                          __nv_bfloat162* __restrict__ hi,
                          __nv_bfloat162* __restrict__ lo, int n4)
{
    int i = blockIdx.x * blockDim.x + threadIdx.x;
    if (i >= n4) return;
    float4 v = x[i];
    uint32_t h0, l0, h1, l1;
    split2(v.x, v.y, h0, l0);
    split2(v.z, v.w, h1, l1);
    hi[2 * i + 0] = *(__nv_bfloat162*)&h0;
    hi[2 * i + 1] = *(__nv_bfloat162*)&h1;
    lo[2 * i + 0] = *(__nv_bfloat162*)&l0;
    lo[2 * i + 1] = *(__nv_bfloat162*)&l1;
}

// ---------------------------------------------------------------------------
// all 4 weights -> transposed hi/lo bf16, one launch (z picks the matrix)
// ---------------------------------------------------------------------------
__global__ void conv_wt4(const float* __restrict__ Wq, const float* __restrict__ Wk,
                         const float* __restrict__ Wv, const float* __restrict__ Wo,
                         __nv_bfloat16* __restrict__ whtBase,
                         __nv_bfloat16* __restrict__ wltBase)
{
    __shared__ float t[32][33];
    const int z = blockIdx.z;
    const float* W = (z == 0) ? Wq : (z == 1) ? Wk : (z == 2) ? Wv : Wo;
    __nv_bfloat16* wht = whtBase + (size_t)z * DM * DM;
    __nv_bfloat16* wlt = wltBase + (size_t)z * DM * DM;

    const int k0 = blockIdx.y * 32, n0 = blockIdx.x * 32;
    const int tx = threadIdx.x, ty = threadIdx.y;
    #pragma unroll
    for (int j = ty; j < 32; j += 8)
        t[j][tx] = W[(size_t)(k0 + j) * DM + n0 + tx];
    __syncthreads();
    #pragma unroll
    for (int j = ty; j < 32; j += 8) {
        float v = t[tx][j];
        __nv_bfloat16 h = __float2bfloat16_rn(v);
        wht[(size_t)(n0 + j) * DM + k0 + tx] = h;
        wlt[(size_t)(n0 + j) * DM + k0 + tx] =
            __float2bfloat16_rn(v - __bfloat162float(h));
    }
}

// ---------------------------------------------------------------------------
// shared HMMA GEMM mainloop (128x128 CTA tile, 8 warps 2x4, K chunk 64)
// ---------------------------------------------------------------------------
#define GP     144
#define OFF_AH 0
#define OFF_AL (128 * GP)
#define OFF_BH (2 * 128 * GP)
#define OFF_BL (3 * 128 * GP)
#define GSMEM  (4 * 128 * GP)              // 73728 B

__device__ __forceinline__ void gemm_mainloop(
    char* smg, uint32_t sb, int tid, int wm, int wn, int lid,
    const char* gAh, const char* gAl, const char* gBh, const char* gBl,
    float acc[4][4][4])
{
    const int a_row = (wm << 6) + (lid & 15);
    const int a_cb  = (lid >> 4) << 4;
    const int b_sub = lid >> 3;
    const int b_row = (wn << 5) + ((b_sub & 1) << 3) + (lid & 7);
    const int b_cb  = (b_sub >> 1) << 4;

    for (int ck = 0; ck < 8; ck++) {
        const size_t koff = (size_t)ck << 7;
        __syncthreads();
        #pragma unroll
        for (int i = 0; i < 4; i++) {
            int idx = tid + (i << 8);
            int r = idx >> 3, cb = (idx & 7) << 4;
            size_t go = (size_t)r * (DM * 2) + koff + cb;
            uint32_t so = r * GP + cb;
            cp16(sb + OFF_AH + so, gAh + go);
            cp16(sb + OFF_AL + so, gAl + go);
            cp16(sb + OFF_BH + so, gBh + go);
            cp16(sb + OFF_BL + so, gBl + go);
        }
        cp_commit();
        cp_wait<0>();
        __syncthreads();

        #pragma unroll
        for (int ks = 0; ks < 4; ks++) {
            const int kb = ks << 5;

            uint32_t ah[4][4], al[4][4];
            #pragma unroll
            for (int mt = 0; mt < 4; mt++) {
                uint32_t ad = sb + (a_row + (mt << 4)) * GP + kb + a_cb;
                ldsm_x4(ah[mt][0], ah[mt][1], ah[mt][2], ah[mt][3], OFF_AH + ad);
                ldsm_x4(al[mt][0], al[mt][1], al[mt][2], al[mt][3], OFF_AL + ad);
            }
            uint32_t bh[4][2], bl[4][2];
            #pragma unroll
            for (int pr = 0; pr < 2; pr++) {
                uint32_t bd = sb + (b_row + (pr << 4)) * GP + kb + b_cb;
                uint32_t r0, r1, r2, r3;
                ldsm_x4(r0, r1, r2, r3, OFF_BH + bd);
                bh[2 * pr][0] = r0; bh[2 * pr + 1][0] = r1;
                bh[2 * pr][1] = r2; bh[2 * pr + 1][1] = r3;
                ldsm_x4(r0, r1, r2, r3, OFF_BL + bd);
                bl[2 * pr][0] = r0; bl[2 * pr + 1][0] = r1;
                bl[2 * pr][1] = r2; bl[2 * pr + 1][1] = r3;
            }

            #pragma unroll
            for (int mt = 0; mt < 4; mt++)
                #pragma unroll
                for (int nt = 0; nt < 4; nt++) {
                    mma16816(acc[mt][nt], ah[mt], bh[nt]);
                    mma16816(acc[mt][nt], ah[mt], bl[nt]);
                    mma16816(acc[mt][nt], al[mt], bh[nt]);
                }
        }
    }
}

// ---------------------------------------------------------------------------
// fused QKV GEMM: grid (4, 192). y<128: Q rows; y in [128,160): K; else V.
// bf16 hi/lo epilogue.
// ---------------------------------------------------------------------------
__global__ __launch_bounds__(256) void qkv_gemm(
    const __nv_bfloat16* __restrict__ tkh, const __nv_bfloat16* __restrict__ tkl,
    const __nv_bfloat16* __restrict__ pth, const __nv_bfloat16* __restrict__ ptl,
    const __nv_bfloat16* __restrict__ wth, const __nv_bfloat16* __restrict__ wtl,
    const float* __restrict__ bq, const float* __restrict__ bk,
    const float* __restrict__ bv,
    __nv_bfloat16* __restrict__ qh, __nv_bfloat16* __restrict__ ql,
    __nv_bfloat16* __restrict__ kh, __nv_bfloat16* __restrict__ kl,
    __nv_bfloat16* __restrict__ vh, __nv_bfloat16* __restrict__ vl)
{
    extern __shared__ char smg[];
    const uint32_t sb = smem_u32(smg);
    const int tid = threadIdx.x, wid = tid >> 5, lid = tid & 31;
    const int wm = wid >> 2, wn = wid & 3;

    const int by = blockIdx.y;
    const __nv_bfloat16 *Ahi, *Alo;
    const float* bias;
    __nv_bfloat16 *Chi, *Clo;
    int widx, mblk;
    if (by < 128)      { Ahi = tkh; Alo = tkl; bias = bq; Chi = qh; Clo = ql; widx = 0; mblk = by; }
    else if (by < 160) { Ahi = pth; Alo = ptl; bias = bk; Chi = kh; Clo = kl; widx = 1; mblk = by - 128; }
    else               { Ahi = pth; Alo = ptl; bias = bv; Chi = vh; Clo = vl; widx = 2; mblk = by - 160; }

    const int m0 = mblk << 7, n0 = blockIdx.x << 7;
    const __nv_bfloat16* Bhi = wth + (size_t)widx * DM * DM;
    const __nv_bfloat16* Blo = wtl + (size_t)widx * DM * DM;

    float acc[4][4][4];
    #pragma unroll
    for (int i = 0; i < 4; i++)
        #pragma unroll
        for (int j = 0; j < 4; j++)
            #pragma unroll
            for (int c = 0; c < 4; c++) acc[i][j][c] = 0.0f;

    gemm_mainloop(smg, sb, tid, wm, wn, lid,
                  (const char*)(Ahi + (size_t)m0 * DM),
                  (const char*)(Alo + (size_t)m0 * DM),
                  (const char*)(Bhi + (size_t)n0 * DM),
                  (const char*)(Blo + (size_t)n0 * DM), acc);

    #pragma unroll
    for (int mt = 0; mt < 4; mt++) {
        const int row0 = m0 + (wm << 6) + (mt << 4) + (lid >> 2);
        #pragma unroll
        for (int nt = 0; nt < 4; nt++) {
            const int col = n0 + (wn << 5) + (nt << 3) + ((lid & 3) << 1);
            const float b0 = bias[col], b1 = bias[col + 1];
            uint32_t h, l;
            split2(acc[mt][nt][0] + b0, acc[mt][nt][1] + b1, h, l);
            *(uint32_t*)&Chi[(size_t)row0 * DM + col] = h;
            *(uint32_t*)&Clo[(size_t)row0 * DM + col] = l;
            split2(acc[mt][nt][2] + b0, acc[mt][nt][3] + b1, h, l);
            *(uint32_t*)&Chi[(size_t)(row0 + 8) * DM + col] = h;
            *(uint32_t*)&Clo[(size_t)(row0 + 8) * DM + col] = l;
        }
    }
}

// ---------------------------------------------------------------------------
// out projection GEMM: fp32 + bias + residual epilogue. grid (4, 128).
// ---------------------------------------------------------------------------
__global__ __launch_bounds__(256) void out_gemm(
    const __nv_bfloat16* __restrict__ Ahi, const __nv_bfloat16* __restrict__ Alo,
    const __nv_bfloat16* __restrict__ Bhi, const __nv_bfloat16* __restrict__ Blo,
    const float* __restrict__ bias, const float* __restrict__ resid,
    float* __restrict__ Cf)
{
    extern __shared__ char smg[];
    const uint32_t sb = smem_u32(smg);
    const int tid = threadIdx.x, wid = tid >> 5, lid = tid & 31;
    const int wm = wid >> 2, wn = wid & 3;
    const int m0 = blockIdx.y << 7, n0 = blockIdx.x << 7;

    float acc[4][4][4];
    #pragma unroll
    for (int i = 0; i < 4; i++)
        #pragma unroll
        for (int j = 0; j < 4; j++)
            #pragma unroll
            for (int c = 0; c < 4; c++) acc[i][j][c] = 0.0f;

    gemm_mainloop(smg, sb, tid, wm, wn, lid,
                  (const char*)(Ahi + (size_t)m0 * DM),
                  (const char*)(Alo + (size_t)m0 * DM),
                  (const char*)(Bhi + (size_t)n0 * DM),
                  (const char*)(Blo + (size_t)n0 * DM), acc);

    #pragma unroll
    for (int mt = 0; mt < 4; mt++) {
        const int row0 = m0 + (wm << 6) + (mt << 4) + (lid >> 2);
        #pragma unroll
        for (int nt = 0; nt < 4; nt++) {
            const int col = n0 + (wn << 5) + (nt << 3) + ((lid & 3) << 1);
            const float b0 = bias[col], b1 = bias[col + 1];
            const float2 r0 = *(const float2*)&resid[(size_t)row0 * DM + col];
            const float2 r1 = *(const float2*)&resid[(size_t)(row0 + 8) * DM + col];
            *(float2*)&Cf[(size_t)row0 * DM + col] =
                make_float2(acc[mt][nt][0] + b0 + r0.x, acc[mt][nt][1] + b1 + r0.y);
            *(float2*)&Cf[(size_t)(row0 + 8) * DM + col] =
                make_float2(acc[mt][nt][2] + b0 + r1.x, acc[mt][nt][3] + b1 + r1.y);
        }
    }
}

// ---------------------------------------------------------------------------
// HMMA flash attention, split-bf16 3-term, block-causal mask,
// cp.async 2-stage K/V pipeline.
// grid (T/64, H, B), 128 threads (4 warps); warp w owns q rows [16w,16w+16).
// smem: Q hi/lo (18432 B) + 2 stages x {Kh,Kl,Vh,Vl} (36864 B each).
// ---------------------------------------------------------------------------
#define ATP      144
#define AQH      0
#define AQL      (64 * ATP)
#define ASTAGE0  (2 * 64 * ATP)            // 18432
#define STG_SZ   (4 * 64 * ATP)            // 36864 per stage
#define SKH      0
#define SKL      (64 * ATP)
#define SVH      (2 * 64 * ATP)
#define SVL      (3 * 64 * ATP)
#define AT_SMEM  (ASTAGE0 + 2 * STG_SZ)    // 92160 B

__global__ __launch_bounds__(128) void attn_hmma(
    const __nv_bfloat16* __restrict__ Qh, const __nv_bfloat16* __restrict__ Ql,
    const __nv_bfloat16* __restrict__ Kh, const __nv_bfloat16* __restrict__ Kl,
    const __nv_bfloat16* __restrict__ Vh, const __nv_bfloat16* __restrict__ Vl,
    __nv_bfloat16* __restrict__ Ch, __nv_bfloat16* __restrict__ Cl)
{
    extern __shared__ char sma[];
    const uint32_t sb = smem_u32(sma);
    const int tid = threadIdx.x, wid = tid >> 5, lid = tid & 31;
    const int b = blockIdx.z, h = blockIdx.y;
    const int t0 = blockIdx.x << 6;

    const int nblocks = ((t0 + 63) >> 8) + 1;
    const char* gkh = (const char*)(Kh + (size_t)b * PP * DM + h * HD);
    const char* gkl = (const char*)(Kl + (size_t)b * PP * DM + h * HD);
    const char* gvh = (const char*)(Vh + (size_t)b * PP * DM + h * HD);
    const char* gvl = (const char*)(Vl + (size_t)b * PP * DM + h * HD);

    // per-thread fill coordinates: 512 16B-chunks per 64x128B tile, 4/thread
    // idx = tid + i*128 : r = idx>>3 (row), c16 = (idx&7)<<4
    // ---- prologue: async-load Q tile + stage 0 K/V ----
    {
        const char* gqh = (const char*)(Qh + (size_t)(b * TT + t0) * DM + h * HD);
        const char* gql = (const char*)(Ql + (size_t)(b * TT + t0) * DM + h * HD);
        #pragma unroll
        for (int i = 0; i < 4; i++) {
            int idx = tid + (i << 7);
            int r = idx >> 3, c16 = (idx & 7) << 4;
            size_t go = (size_t)r * 1024 + c16;
            uint32_t so = r * ATP + c16;
            cp16(sb + AQH + so, gqh + go);
            cp16(sb + AQL + so, gql + go);
            cp16(sb + ASTAGE0 + SKH + so, gkh + go);
            cp16(sb + ASTAGE0 + SKL + so, gkl + go);
            cp16(sb + ASTAGE0 + SVH + so, gvh + go);
            cp16(sb + ASTAGE0 + SVL + so, gvl + go);
        }
        cp_commit();
    }

    float S[8][4], O[8][4];
    #pragma unroll
    for (int nt = 0; nt < 8; nt++)
        #pragma unroll
        for (int e = 0; e < 4; e++) O[nt][e] = 0.0f;
    float mrun0 = -1e30f, mrun1 = -1e30f, lrun0 = 0.0f, lrun1 = 0.0f;

    const uint32_t a_ad0 = sb + AQH + ((wid << 4) + (lid & 15)) * ATP + ((lid >> 4) << 4);
    const uint32_t b_row = ((lid >> 3) & 1) * 8 + (lid & 7);
    const uint32_t b_cb  = (lid >> 4) << 4;

    const int trow = t0 + (wid << 4) + (lid >> 2);
    const int lim0 = trow >> 2;
    const int lim1 = (trow + 8) >> 2;

    for (int kb = 0; kb < nblocks; kb++) {
        const int p0 = kb << 6;
        const uint32_t stg = ASTAGE0 + (uint32_t)(kb & 1) * STG_SZ;

        // prefetch next K/V stage
        if (kb + 1 < nblocks) {
            const uint32_t nstg = ASTAGE0 + (uint32_t)((kb + 1) & 1) * STG_SZ;
            const size_t pb = (size_t)(p0 + 64) * 1024;
            #pragma unroll
            for (int i = 0; i < 4; i++) {
                int idx = tid + (i << 7);
                int r = idx >> 3, c16 = (idx & 7) << 4;
                size_t go = pb + (size_t)r * 1024 + c16;
                uint32_t so = r * ATP + c16;
                cp16(sb + nstg + SKH + so, gkh + go);
                cp16(sb + nstg + SKL + so, gkl + go);
                cp16(sb + nstg + SVH + so, gvh + go);
                cp16(sb + nstg + SVL + so, gvl + go);
            }
            cp_commit();
            cp_wait<1>();      // current stage (older group) complete
        } else {
            cp_wait<0>();
        }
        __syncthreads();

        // ---- scores S = Q K^T via 3-term HMMA ----
        #pragma unroll
        for (int nt = 0; nt < 8; nt++)
            #pragma unroll
            for (int e = 0; e < 4; e++) S[nt][e] = 0.0f;

        #pragma unroll
        for (int ks = 0; ks < 4; ks++) {
            const uint32_t kbyte = ks << 5;
            uint32_t ah[4], al[4];
            ldsm_x4(ah[0], ah[1], ah[2], ah[3], a_ad0 + kbyte);
            ldsm_x4(al[0], al[1], al[2], al[3], a_ad0 + (AQL - AQH) + kbyte);
            #pragma unroll
            for (int ntp = 0; ntp < 4; ntp++) {
                uint32_t bd = sb + stg + SKH + ((ntp << 4) + b_row) * ATP + kbyte + b_cb;
                uint32_t r0, r1, r2, r3;
                uint32_t bh0[2], bh1[2], bl0[2], bl1[2];
                ldsm_x4(r0, r1, r2, r3, bd);
                bh0[0] = r0; bh1[0] = r1; bh0[1] = r2; bh1[1] = r3;
                ldsm_x4(r0, r1, r2, r3, bd + (SKL - SKH));
                bl0[0] = r0; bl1[0] = r1; bl0[1] = r2; bl1[1] = r3;
                mma16816(S[2 * ntp],     ah, bh0);
                mma16816(S[2 * ntp],     ah, bl0);
                mma16816(S[2 * ntp],     al, bh0);
                mma16816(S[2 * ntp + 1], ah, bh1);
                mma16816(S[2 * ntp + 1], ah, bl1);
                mma16816(S[2 * ntp + 1], al, bh1);
            }
        }

        #pragma unroll
        for (int nt = 0; nt < 8; nt++)
            #pragma unroll
            for (int e = 0; e < 4; e++) S[nt][e] *= 0.125f;

        if (kb == nblocks - 1) {
            const int cb = p0 + ((lid & 3) << 1);
            #pragma unroll
            for (int nt = 0; nt < 8; nt++) {
                const int c0 = cb + (nt << 3), c1 = c0 + 1;
                if (c0 > lim0) S[nt][0] = -1e30f;
                if (c1 > lim0) S[nt][1] = -1e30f;
                if (c0 > lim1) S[nt][2] = -1e30f;
                if (c1 > lim1) S[nt][3] = -1e30f;
            }
        }

        // ---- online softmax (rows trow, trow+8) ----
        float rm0 = -1e30f, rm1 = -1e30f;
        #pragma unroll
        for (int nt = 0; nt < 8; nt++) {
            rm0 = fmaxf(rm0, fmaxf(S[nt][0], S[nt][1]));
            rm1 = fmaxf(rm1, fmaxf(S[nt][2], S[nt][3]));
        }
        rm0 = fmaxf(rm0, __shfl_xor_sync(0xffffffffu, rm0, 1));
        rm0 = fmaxf(rm0, __shfl_xor_sync(0xffffffffu, rm0, 2));
        rm1 = fmaxf(rm1, __shfl_xor_sync(0xffffffffu, rm1, 1));
        rm1 = fmaxf(rm1, __shfl_xor_sync(0xffffffffu, rm1, 2));

        const float mn0 = fmaxf(mrun0, rm0), mn1 = fmaxf(mrun1, rm1);
        const float al0 = __expf(mrun0 - mn0), al1 = __expf(mrun1 - mn1);
        float s0 = 0.0f, s1 = 0.0f;
        #pragma unroll
        for (int nt = 0; nt < 8; nt++) {
            float p0e = __expf(S[nt][0] - mn0);
            float p1e = __expf(S[nt][1] - mn0);
            float p2e = __expf(S[nt][2] - mn1);
            float p3e = __expf(S[nt][3] - mn1);
            S[nt][0] = p0e; S[nt][1] = p1e; S[nt][2] = p2e; S[nt][3] = p3e;
            s0 += p0e + p1e; s1 += p2e + p3e;
            O[nt][0] *= al0; O[nt][1] *= al0;
            O[nt][2] *= al1; O[nt][3] *= al1;
        }
        s0 += __shfl_xor_sync(0xffffffffu, s0, 1);
        s0 += __shfl_xor_sync(0xffffffffu, s0, 2);
        s1 += __shfl_xor_sync(0xffffffffu, s1, 1);
        s1 += __shfl_xor_sync(0xffffffffu, s1, 2);
        lrun0 = lrun0 * al0 + s0; lrun1 = lrun1 * al1 + s1;
        mrun0 = mn0; mrun1 = mn1;

        // ---- O += P V ----
        #pragma unroll
        for (int ks = 0; ks < 4; ks++) {
            const int nt0 = 2 * ks, nt1 = 2 * ks + 1;
            uint32_t aph[4], apl[4];
            split2(S[nt0][0], S[nt0][1], aph[0], apl[0]);
            split2(S[nt0][2], S[nt0][3], aph[1], apl[1]);
            split2(S[nt1][0], S[nt1][1], aph[2], apl[2]);
            split2(S[nt1][2], S[nt1][3], aph[3], apl[3]);

            #pragma unroll
            for (int nv = 0; nv < 4; nv++) {
                uint32_t vd = sb + stg + SVH + ((ks << 4) + b_row) * ATP + (nv << 5) + b_cb;
                uint32_t r0, r1, r2, r3;
                uint32_t vh0[2], vh1[2], vl0[2], vl1[2];
                ldsm_x4_t(r0, r1, r2, r3, vd);
                vh0[0] = r0; vh0[1] = r1; vh1[0] = r2; vh1[1] = r3;
                ldsm_x4_t(r0, r1, r2, r3, vd + (SVL - SVH));
                vl0[0] = r0; vl0[1] = r1; vl1[0] = r2; vl1[1] = r3;
                mma16816(O[2 * nv],     aph, vh0);
                mma16816(O[2 * nv],     aph, vl0);
                mma16816(O[2 * nv],     apl, vh0);
                mma16816(O[2 * nv + 1], aph, vh1);
                mma16816(O[2 * nv + 1], aph, vl1);
                mma16816(O[2 * nv + 1], apl, vh1);
            }
        }
        __syncthreads();   // all reads of stage done before its refill (kb+2)
    }

    // ---- normalize + write ctx hi/lo ----
    const float inv0 = 1.0f / lrun0, inv1 = 1.0f / lrun1;
    const size_t row0 = (size_t)(b * TT) + trow;
    #pragma unroll
    for (int nt = 0; nt < 8; nt++) {
        const int col = h * HD + (nt << 3) + ((lid & 3) << 1);
        uint32_t hh, ll;
        split2(O[nt][0] * inv0, O[nt][1] * inv0, hh, ll);
        *(uint32_t*)&Ch[row0 * DM + col] = hh;
        *(uint32_t*)&Cl[row0 * DM + col] = ll;
        split2(O[nt][2] * inv1, O[nt][3] * inv1, hh, ll);
        *(uint32_t*)&Ch[(row0 + 8) * DM + col] = hh;
        *(uint32_t*)&Cl[(row0 + 8) * DM + col] = ll;
    }
}

// ---------------------------------------------------------------------------
extern "C" void kernel_launch(void* const* d_in, const int* in_sizes, int n_in,
                              void* d_out, int out_size)
{
    (void)in_sizes; (void)n_in; (void)out_size;
    const float* tok   = (const float*)d_in[0];
    const float* patch = (const float*)d_in[1];
    const float* Wq    = (const float*)d_in[2];
    const float* Wk    = (const float*)d_in[3];
    const float* Wv    = (const float*)d_in[4];
    const float* bq    = (const float*)d_in[5];
    const float* bk    = (const float*)d_in[6];
    const float* bv    = (const float*)d_in[7];
    const float* Wo    = (const float*)d_in[8];
    const float* bo    = (const float*)d_in[9];
    float* out = (float*)d_out;

    __nv_bfloat16 *qh, *ql, *kh, *kl, *vh, *vl;
    __nv_bfloat16 *tkh, *tkl, *pth, *ptl, *cxh, *cxl, *wth, *wtl;
    cudaGetSymbolAddress((void**)&qh,  g_Qh);
    cudaGetSymbolAddress((void**)&ql,  g_Ql);
    cudaGetSymbolAddress((void**)&kh,  g_Kh);
    cudaGetSymbolAddress((void**)&kl,  g_Kl);
    cudaGetSymbolAddress((void**)&vh,  g_Vh);
    cudaGetSymbolAddress((void**)&vl,  g_Vl);
    cudaGetSymbolAddress((void**)&tkh, g_tok_hi);
    cudaGetSymbolAddress((void**)&tkl, g_tok_lo);
    cudaGetSymbolAddress((void**)&pth, g_pat_hi);
    cudaGetSymbolAddress((void**)&ptl, g_pat_lo);
    cudaGetSymbolAddress((void**)&cxh, g_ctx_hi);
    cudaGetSymbolAddress((void**)&cxl, g_ctx_lo);
    cudaGetSymbolAddress((void**)&wth, g_Wt_hi);
    cudaGetSymbolAddress((void**)&wtl, g_Wt_lo);

    static bool attr_set = false;
    if (!attr_set) {
        cudaFuncSetAttribute(qkv_gemm,
                             cudaFuncAttributeMaxDynamicSharedMemorySize, GSMEM);
        cudaFuncSetAttribute(out_gemm,
                             cudaFuncAttributeMaxDynamicSharedMemorySize, GSMEM);
        cudaFuncSetAttribute(attn_hmma,
                             cudaFuncAttributeMaxDynamicSharedMemorySize, AT_SMEM);
        attr_set = true;
    }

    const int nTok4 = BB * TT * DM / 4;
    const int nPat4 = BB * PP * DM / 4;

    // split inputs into bf16 hi/lo
    conv_hilo<<<nTok4 / 256, 256>>>((const float4*)tok,
        (__nv_bfloat162*)tkh, (__nv_bfloat162*)tkl, nTok4);
    conv_hilo<<<nPat4 / 256, 256>>>((const float4*)patch,
        (__nv_bfloat162*)pth, (__nv_bfloat162*)ptl, nPat4);
    conv_wt4<<<dim3(16, 16, 4), dim3(32, 8)>>>(Wq, Wk, Wv, Wo, wth, wtl);

    // fused Q/K/V projections -> bf16 hi/lo
    qkv_gemm<<<dim3(4, 192), 256, GSMEM>>>(
        tkh, tkl, pth, ptl, wth, wtl, bq, bk, bv,
        qh, ql, kh, kl, vh, vl);

    // HMMA flash attention -> ctx hi/lo
    attn_hmma<<<dim3(TT / 64, NH, BB), 128, AT_SMEM>>>(
        qh, ql, kh, kl, vh, vl, cxh, cxl);

    // out projection + bias + residual -> fp32 output
    out_gemm<<<dim3(4, 128), 256, GSMEM>>>(
        cxh, cxl, wth + 3 * (size_t)DM * DM, wtl + 3 * (size_t)DM * DM,
        bo, tok, out);
}